// round 12
// baseline (speedup 1.0000x reference)
#include <cuda_runtime.h>
#include <math.h>

#define NN 100000
#define NE 1600000
#define NG 1000
#define NBLK 391   // ceil(NN/256)
#define SLOT 33
typedef unsigned long long ull;

// ---- scratch (static device globals; no allocation) ----
__device__ __align__(128) float g_posg[NN * 2];
__device__ __align__(128) float g_ncs [NN * 2];
__device__ __align__(128) float g_nacc[NN * 4];
__device__ __align__(128) float g_gacc[NG * 4];
__device__ int   g_deg[NN];
__device__ int   g_rowstart[NN];
__device__ int   g_cursor[NN];
__device__ int   g_psum[512];
__device__ __align__(128) float4 g_rec[NE];   // col(bits), s1*invd, c1, s1*d-ish
__device__ int   g_erow[NE];
__device__ __align__(128) float g_xs  [NN * 16];
__device__ __align__(128) float g_xrot[NN * 32];
__device__ __align__(128) float g_y   [NN * 32];
__device__ __align__(128) float g_as  [NN * 16];
__device__ __align__(128) float g_gate[NN * 16];
__device__ __align__(128) float g_aggR[NN * 32];
__device__ __align__(128) float g_aggS[NN * 16];

__device__ __forceinline__ void red4(float* a, float x, float y, float z, float w) {
    asm volatile("red.global.add.v4.f32 [%0], {%1,%2,%3,%4};"
                 :: "l"(a), "f"(x), "f"(y), "f"(z), "f"(w));
}
__device__ __forceinline__ void red1(float* a, float v) {
    asm volatile("red.global.add.f32 [%0], %1;" :: "l"(a), "f"(v));
}
__device__ __forceinline__ float lrelu(float x) { return x > 0.f ? x : 0.01f * x; }
__device__ __forceinline__ ull fma2(ull a, ull b, ull c) {
    ull d; asm("fma.rn.f32x2 %0,%1,%2,%3;" : "=l"(d) : "l"(a), "l"(b), "l"(c)); return d;
}
__device__ __forceinline__ ull pk2(float x, float y) {
    ull r; asm("mov.b64 %0,{%1,%2};" : "=l"(r) : "f"(x), "f"(y)); return r;
}
__device__ __forceinline__ float2 upk(ull v) {
    float2 r; asm("mov.b64 {%0,%1},%2;" : "=f"(r.x), "=f"(r.y) : "l"(v)); return r;
}

// ---- zero ----
__global__ void kZero(float* out) {
    int i = blockIdx.x * blockDim.x + threadIdx.x;
    for (int t = i; t < NN * 4; t += gridDim.x * blockDim.x) g_nacc[t] = 0.f;
    for (int t = i; t < NN; t += gridDim.x * blockDim.x) g_deg[t] = 0;
    if (i < NG * 4) g_gacc[i] = 0.f;
    if (i < NG * 6) out[i] = 0.f;
}

// edge-grid: per-edge degree histogram; first NN threads also do graph mean acc
__global__ void kGraphAcc(const float* __restrict__ pos, const int* __restrict__ batch,
                          const int* __restrict__ ei) {
    int n = blockIdx.x * blockDim.x + threadIdx.x;
    if (n < NN)
        red4(&g_gacc[batch[n] * 4], pos[2 * n], pos[2 * n + 1], 1.f, 0.f);
    if (n < NE)
        atomicAdd(&g_deg[ei[n]], 1);
}

// fused: center/rot (independent) + block-local scan of degrees
__global__ void kCenterScan(const float* __restrict__ pos, const int* __restrict__ batch) {
    __shared__ int s[256];
    int n = blockIdx.x * 256 + threadIdx.x;
    int v = (n < NN) ? g_deg[n] : 0;
    s[threadIdx.x] = v; __syncthreads();
    for (int d = 1; d < 256; d <<= 1) {
        int t = (threadIdx.x >= d) ? s[threadIdx.x - d] : 0;
        __syncthreads();
        s[threadIdx.x] += t;
        __syncthreads();
    }
    if (n < NN) g_rowstart[n] = s[threadIdx.x] - v;
    if (threadIdx.x == 255) g_psum[blockIdx.x] = s[255];
    if (n >= NN) return;
    float4 ga = *(const float4*)&g_gacc[batch[n] * 4];
    float inv = 1.f / fmaxf(ga.z, 1.f);
    float px = pos[2 * n]     - ga.x * inv;
    float py = pos[2 * n + 1] - ga.y * inv;
    g_posg[2 * n] = px; g_posg[2 * n + 1] = py;
    float r2 = px * px + py * py;
    float c = 1.f, sv = 0.f;
    if (r2 > 0.f) { float ir = rsqrtf(r2); c = px * ir; sv = py * ir; }
    g_ncs[2 * n] = c; g_ncs[2 * n + 1] = sv;
}

__global__ void kScanB() {
    __shared__ int s[512];
    int t = threadIdx.x;
    int v = (t < NBLK) ? g_psum[t] : 0;
    s[t] = v; __syncthreads();
    for (int d = 1; d < 512; d <<= 1) {
        int u = (t >= d) ? s[t - d] : 0;
        __syncthreads();
        s[t] += u;
        __syncthreads();
    }
    if (t < NBLK) g_psum[t] = s[t] - v;
}

__global__ void kScanC() {
    int n = blockIdx.x * 256 + threadIdx.x;
    if (n >= NN) return;
    int rs = g_rowstart[n] + g_psum[blockIdx.x];
    g_rowstart[n] = rs;
    g_cursor[n] = rs;
}

// ---- per-edge geometry + CSR fill ----
__global__ void kEdgeFill(const int* __restrict__ ei) {
    int e = blockIdx.x * blockDim.x + threadIdx.x;
    if (e >= NE) return;
    int r = ei[e], c = ei[NE + e];
    float vx = g_posg[2 * r] - g_posg[2 * c];
    float vy = g_posg[2 * r + 1] - g_posg[2 * c + 1];
    float r2 = vx * vx + vy * vy;
    float d = 0.f, cc = 1.f, ss = 0.f;
    if (r2 > 0.f) { float ir = rsqrtf(r2); d = r2 * ir; cc = vx * ir; ss = vy * ir; }
    float invd = 1.41421356237f / (d + 1e-8f);
    float s1, c1;
    __sincosf(3.14159265358979f * d, &s1, &c1);
    int pos = atomicAdd(&g_cursor[r], 1);
    // t1 = s1/invd = s1*(d+eps)/sqrt2  (division-free)
    g_rec[pos] = make_float4(__int_as_float(c), s1 * invd, c1,
                             s1 * (d + 1e-8f) * 0.70710678118f);
    g_erow[pos] = r;
    red4(&g_nacc[r * 4], 1.f, d, cc, ss);
}

// ---- fused node kernel: post(prev) / init + pre(layer); zero agg ----
__global__ void kNodeFuse(const float* __restrict__ wse, const float* __restrict__ bse,
                          const float* __restrict__ Wemb,
                          const float* __restrict__ Wmix, const float* __restrict__ Wgate,
                          const float* __restrict__ bgate, const float* __restrict__ Ws1,
                          int layer) {
    __shared__ __align__(16) ull sMix2[256];   // Wmix[i][j] duplicated into both halves
    __shared__ __align__(16) ull sGate2[128], sWs2[128];
    __shared__ ull sbg2[8];
    for (int t = threadIdx.x; t < 256; t += blockDim.x) {
        float w = Wmix[layer * 256 + t];
        sMix2[t] = pk2(w, w);
    }
    for (int t = threadIdx.x; t < 128; t += blockDim.x) {
        sGate2[t] = ((const ull*)(Wgate + layer * 256))[t];
        sWs2[t]   = ((const ull*)(Ws1 + layer * 512))[t];
    }
    if (threadIdx.x < 8) sbg2[threadIdx.x] = ((const ull*)(bgate + layer * 16))[threadIdx.x];
    __syncthreads();
    int n = blockIdx.x * blockDim.x + threadIdx.x;
    if (n >= NN) return;

    float xs[16], xr[32];
    if (layer == 0) {
        float4 a = *(const float4*)&g_nacc[n * 4];
        float deg = fmaxf(a.x, 1.f);
        float invdeg = 1.f / deg;
        float dmean = a.y * invdeg;
        float Cm = a.z * invdeg, Sm = a.w * invdeg;
#pragma unroll
        for (int i = 0; i < 16; i++) xs[i] = lrelu(dmean * wse[i] + bse[i]);
#pragma unroll
        for (int j = 0; j < 16; j++) {
            float w0 = Wemb[2 * j], w1 = Wemb[2 * j + 1];
            xr[2 * j]     = Cm * w0 - Sm * w1;
            xr[2 * j + 1] = Sm * w0 + Cm * w1;
        }
        g_nacc[n * 4] = invdeg;
        float4* po = (float4*)&g_xs[n * 16];
#pragma unroll
        for (int q = 0; q < 4; q++) po[q] = make_float4(xs[4*q], xs[4*q+1], xs[4*q+2], xs[4*q+3]);
        float4* pr = (float4*)&g_xrot[n * 32];
#pragma unroll
        for (int q = 0; q < 8; q++) pr[q] = make_float4(xr[4*q], xr[4*q+1], xr[4*q+2], xr[4*q+3]);
    } else {
        const float4* p = (const float4*)&g_xs[n * 16];
#pragma unroll
        for (int q = 0; q < 4; q++) { float4 v = p[q]; xs[4*q]=v.x; xs[4*q+1]=v.y; xs[4*q+2]=v.z; xs[4*q+3]=v.w; }
        const float4* pr = (const float4*)&g_xrot[n * 32];
#pragma unroll
        for (int q = 0; q < 8; q++) { float4 v = pr[q]; xr[4*q]=v.x; xr[4*q+1]=v.y; xr[4*q+2]=v.z; xr[4*q+3]=v.w; }
        float invd = g_nacc[n * 4];
#pragma unroll
        for (int j = 0; j < 16; j++) {
            float gt = g_gate[n * 16 + j] * invd;
            xr[2 * j]     += gt * g_aggR[n * 32 + 2 * j];
            xr[2 * j + 1] += gt * g_aggR[n * 32 + 2 * j + 1];
        }
#pragma unroll
        for (int i = 0; i < 16; i++) xs[i] += g_aggS[n * 16 + i] * invd;
        float4* po = (float4*)&g_xs[n * 16];
#pragma unroll
        for (int q = 0; q < 4; q++) po[q] = make_float4(xs[4*q], xs[4*q+1], xs[4*q+2], xs[4*q+3]);
        float4* pw = (float4*)&g_xrot[n * 32];
#pragma unroll
        for (int q = 0; q < 8; q++) pw[q] = make_float4(xr[4*q], xr[4*q+1], xr[4*q+2], xr[4*q+3]);
    }

    // y = Wmix @ x_rot  (packed, vectorized weight loads)
    ull xr2[16];
#pragma unroll
    for (int j = 0; j < 16; j++) xr2[j] = pk2(xr[2 * j], xr[2 * j + 1]);
    ull* yo2 = (ull*)&g_y[n * 32];
#pragma unroll
    for (int i = 0; i < 16; i++) {
        ull acc = 0ull;
        const ulonglong2* wm = (const ulonglong2*)(sMix2 + i * 16);
#pragma unroll
        for (int j = 0; j < 8; j++) {
            ulonglong2 wp = wm[j];
            acc = fma2(wp.x, xr2[2 * j], acc);
            acc = fma2(wp.y, xr2[2 * j + 1], acc);
        }
        yo2[i] = acc;
    }
    ull gt2[8], as2[8];
#pragma unroll
    for (int i = 0; i < 8; i++) { gt2[i] = sbg2[i]; as2[i] = 0ull; }
#pragma unroll
    for (int k = 0; k < 16; k++) {
        ull xv2 = pk2(xs[k], xs[k]);
        const ulonglong2* wg = (const ulonglong2*)(sGate2 + k * 8);
        const ulonglong2* ws = (const ulonglong2*)(sWs2 + k * 8);
#pragma unroll
        for (int i = 0; i < 4; i++) {
            ulonglong2 wgp = wg[i], wsp = ws[i];
            gt2[2 * i]     = fma2(xv2, wgp.x, gt2[2 * i]);
            gt2[2 * i + 1] = fma2(xv2, wgp.y, gt2[2 * i + 1]);
            as2[2 * i]     = fma2(xv2, wsp.x, as2[2 * i]);
            as2[2 * i + 1] = fma2(xv2, wsp.y, as2[2 * i + 1]);
        }
    }
#pragma unroll
    for (int i = 0; i < 8; i++) {
        float2 gv = upk(gt2[i]);
        g_gate[n * 16 + 2 * i]     = 1.f / (1.f + __expf(-gv.x));
        g_gate[n * 16 + 2 * i + 1] = 1.f / (1.f + __expf(-gv.y));
        ((ull*)&g_as[n * 16])[i] = as2[i];
    }
    // zero accumulators for this layer's edge pass
    float4 z = make_float4(0.f, 0.f, 0.f, 0.f);
    float4* ar = (float4*)&g_aggR[n * 32];
#pragma unroll
    for (int q = 0; q < 8; q++) ar[q] = z;
    float4* as4 = (float4*)&g_aggS[n * 16];
#pragma unroll
    for (int q = 0; q < 4; q++) as4[q] = z;
}

// ---- per-edge layer (hot): warp = 32 CSR edges; early shuffle-prefetch + split matvec ----
__global__ void __launch_bounds__(128) kEdgeLayerC(
                           const float* __restrict__ Wg, const float* __restrict__ bg,
                           const float* __restrict__ Ws1, const float* __restrict__ bs1,
                           int layer) {
    __shared__ __align__(16) ull sWg2[128], sWs2[128];
    __shared__ ull sbg2[8], sbs2[8];
    __shared__ float smG[4][32 * SLOT];
    __shared__ int scol[4][32], srow[4][32];
    for (int t = threadIdx.x; t < 128; t += blockDim.x) {
        sWg2[t] = ((const ull*)(Wg + layer * 256))[t];
        sWs2[t] = ((const ull*)(Ws1 + layer * 512 + 256))[t];
    }
    if (threadIdx.x < 8) {
        sbg2[threadIdx.x] = ((const ull*)(bg + layer * 16))[threadIdx.x];
        sbs2[threadIdx.x] = ((const ull*)(bs1 + layer * 16))[threadIdx.x];
    }
    __syncthreads();
    int w = threadIdx.x >> 5;
    int lane = threadIdx.x & 31;
    int p = blockIdx.x * 128 + threadIdx.x;   // NE % 128 == 0
    bool sl = (lane < 16);

    float4 rec = g_rec[p];
    int myc = __float_as_int(rec.x);
    int myr = g_erow[p];
    scol[w][lane] = myc;
    srow[w][lane] = myr;

    // ---- early prefetch of half-0 gathers (cols via shuffle; overlaps phase-1 chain) ----
    float yv[16], av[16];
#pragma unroll
    for (int e = 0; e < 16; e++) {
        int c = __shfl_sync(0xffffffffu, myc, e);
        yv[e] = g_y[(size_t)c * 32 + lane];
        av[e] = sl ? g_as[(size_t)c * 16 + lane] : 0.f;
    }

    // ---- phase 1: bessel + split matvec (g-pass then bs-pass) ----
    float emb[16];
    {
        float s1p = rec.y, c1 = rec.z, t1 = rec.w;
        emb[0] = s1p;
        float sk = s1p, ck = c1;
#pragma unroll
        for (int k = 1; k < 16; k++) {
            float sn = fmaf(sk, c1,  ck * s1p);
            float cn = fmaf(ck, c1, -sk * t1);
            emb[k] = sn; sk = sn; ck = cn;
        }
    }
    float* slot = &smG[w][lane * SLOT];
    {
        ull g2[8];
#pragma unroll
        for (int i = 0; i < 8; i++) g2[i] = sbg2[i];
#pragma unroll
        for (int k = 0; k < 16; k++) {
            ull dv2 = pk2(emb[k], emb[k]);
            const ulonglong2* wg = (const ulonglong2*)(sWg2 + k * 8);
#pragma unroll
            for (int i = 0; i < 4; i++) {
                ulonglong2 wgp = wg[i];
                g2[2 * i]     = fma2(dv2, wgp.x, g2[2 * i]);
                g2[2 * i + 1] = fma2(dv2, wgp.y, g2[2 * i + 1]);
            }
        }
#pragma unroll
        for (int i = 0; i < 8; i++) {
            float2 gv = upk(g2[i]);
            slot[2 * i]     = gv.x;
            slot[2 * i + 1] = gv.y;
        }
    }
    {
        ull b2[8];
#pragma unroll
        for (int i = 0; i < 8; i++) b2[i] = sbs2[i];
#pragma unroll
        for (int k = 0; k < 16; k++) {
            ull dv2 = pk2(emb[k], emb[k]);
            const ulonglong2* ws = (const ulonglong2*)(sWs2 + k * 8);
#pragma unroll
            for (int i = 0; i < 4; i++) {
                ulonglong2 wsp = ws[i];
                b2[2 * i]     = fma2(dv2, wsp.x, b2[2 * i]);
                b2[2 * i + 1] = fma2(dv2, wsp.y, b2[2 * i + 1]);
            }
        }
#pragma unroll
        for (int i = 0; i < 8; i++) {
            float2 bv = upk(b2[i]);
            slot[16 + 2 * i]     = bv.x;
            slot[16 + 2 * i + 1] = bv.y;
        }
    }
    __syncwarp();

    // ---- phase 2: accumulate half 0 (prefetched), prefetch+accumulate half 1 ----
    const float* smw = smG[w];
    const int* colw = scol[w];
    const int* roww = srow[w];
    int gidx = lane >> 1;
    float accR = 0.f, accS = 0.f;
    int cur = roww[0];
#pragma unroll
    for (int e = 0; e < 16; e++) {
        int r = roww[e];
        if (r != cur) {
            red1(&g_aggR[(size_t)cur * 32 + lane], accR);
            if (sl) red1(&g_aggS[(size_t)cur * 16 + lane], accS);
            accR = 0.f; accS = 0.f; cur = r;
        }
        float gv = smw[e * SLOT + gidx];
        accR = fmaf(gv, yv[e], accR);
        if (sl) accS += lrelu(av[e] + smw[e * SLOT + 16 + lane]);
    }
#pragma unroll
    for (int e = 0; e < 16; e++) {
        int c = colw[16 + e];
        yv[e] = g_y[(size_t)c * 32 + lane];
        av[e] = sl ? g_as[(size_t)c * 16 + lane] : 0.f;
    }
#pragma unroll
    for (int e = 16; e < 32; e++) {
        int r = roww[e];
        if (r != cur) {
            red1(&g_aggR[(size_t)cur * 32 + lane], accR);
            if (sl) red1(&g_aggS[(size_t)cur * 16 + lane], accS);
            accR = 0.f; accS = 0.f; cur = r;
        }
        float gv = smw[e * SLOT + gidx];
        accR = fmaf(gv, yv[e - 16], accR);
        if (sl) accS += lrelu(av[e - 16] + smw[e * SLOT + 16 + lane]);
    }
    red1(&g_aggR[(size_t)cur * 32 + lane], accR);
    if (sl) red1(&g_aggS[(size_t)cur * 16 + lane], accS);
}

// ---- readout: final post + rotate out + 48->144->6 MLP (f32x2) + graph scatter ----
__global__ void __launch_bounds__(256) kOut(
                     const float* __restrict__ W1, const float* __restrict__ b1,
                     const float* __restrict__ W2, const float* __restrict__ b2,
                     const int* __restrict__ batch, float* __restrict__ out) {
    __shared__ __align__(16) float sW1[48 * 144];
    __shared__ __align__(16) float sW2[144 * 6];
    __shared__ __align__(16) float sb1[144];
    __shared__ float sb2[8];
    for (int t = threadIdx.x; t < 48 * 144; t += blockDim.x) sW1[t] = W1[t];
    for (int t = threadIdx.x; t < 144 * 6; t += blockDim.x) sW2[t] = W2[t];
    for (int t = threadIdx.x; t < 144; t += blockDim.x) sb1[t] = b1[t];
    if (threadIdx.x < 6) sb2[threadIdx.x] = b2[threadIdx.x];
    if (threadIdx.x >= 6 && threadIdx.x < 8) sb2[threadIdx.x] = 0.f;
    __syncthreads();
    int n = blockIdx.x * blockDim.x + threadIdx.x;
    if (n >= NN) return;
    float invd = g_nacc[n * 4];
    float xc[48];
#pragma unroll
    for (int i = 0; i < 16; i++)
        xc[i] = g_xs[n * 16 + i] + g_aggS[n * 16 + i] * invd;
    float cc = g_ncs[2 * n], ss = g_ncs[2 * n + 1];
#pragma unroll
    for (int j = 0; j < 16; j++) {
        float gt = g_gate[n * 16 + j] * invd;
        float x0 = g_xrot[n * 32 + 2 * j]     + gt * g_aggR[n * 32 + 2 * j];
        float x1 = g_xrot[n * 32 + 2 * j + 1] + gt * g_aggR[n * 32 + 2 * j + 1];
        xc[16 + 2 * j]     = cc * x0 - ss * x1;
        xc[16 + 2 * j + 1] = ss * x0 + cc * x1;
    }
    ull u2[3];
    u2[0] = pk2(sb2[0], sb2[1]);
    u2[1] = pk2(sb2[2], sb2[3]);
    u2[2] = pk2(sb2[4], sb2[5]);
    for (int o = 0; o < 144; o += 4) {
        const ull* wb = (const ull*)&sb1[o];
        ull h01 = wb[0], h23 = wb[1];
#pragma unroll
        for (int k = 0; k < 48; k++) {
            const ull* wp = (const ull*)&sW1[k * 144 + o];
            ull xv2 = pk2(xc[k], xc[k]);
            h01 = fma2(xv2, wp[0], h01);
            h23 = fma2(xv2, wp[1], h23);
        }
        float2 ha = upk(h01), hb = upk(h23);
        float hv[4] = {lrelu(ha.x), lrelu(ha.y), lrelu(hb.x), lrelu(hb.y)};
#pragma unroll
        for (int j = 0; j < 4; j++) {
            ull hj2 = pk2(hv[j], hv[j]);
            const ull* w2p = (const ull*)&sW2[(o + j) * 6];
            u2[0] = fma2(hj2, w2p[0], u2[0]);
            u2[1] = fma2(hj2, w2p[1], u2[1]);
            u2[2] = fma2(hj2, w2p[2], u2[2]);
        }
    }
    int b = batch[n];
    float2 ua = upk(u2[0]), ub = upk(u2[1]), uc = upk(u2[2]);
    atomicAdd(&out[b * 6 + 0], ua.x);
    atomicAdd(&out[b * 6 + 1], ua.y);
    atomicAdd(&out[b * 6 + 2], ub.x);
    atomicAdd(&out[b * 6 + 3], ub.y);
    atomicAdd(&out[b * 6 + 4], uc.x);
    atomicAdd(&out[b * 6 + 5], uc.y);
}

extern "C" void kernel_launch(void* const* d_in, const int* in_sizes, int n_in,
                              void* d_out, int out_size) {
    const float* pos   = (const float*)d_in[0];
    const float* Wemb  = (const float*)d_in[1];
    const float* wse   = (const float*)d_in[2];
    const float* bse   = (const float*)d_in[3];
    const float* Wg    = (const float*)d_in[4];
    const float* bg    = (const float*)d_in[5];
    const float* Wmix  = (const float*)d_in[6];
    const float* Wgate = (const float*)d_in[7];
    const float* bgate = (const float*)d_in[8];
    const float* Ws1   = (const float*)d_in[9];
    const float* bs1   = (const float*)d_in[10];
    const float* W1    = (const float*)d_in[11];
    const float* b1    = (const float*)d_in[12];
    const float* W2    = (const float*)d_in[13];
    const float* b2    = (const float*)d_in[14];
    const int*   ei    = (const int*)d_in[15];
    const int*   batch = (const int*)d_in[16];
    float* out = (float*)d_out;

    int nb = (NN + 255) / 256;
    int eb = (NE + 255) / 256;

    kZero<<<1563, 256>>>(out);
    kGraphAcc<<<eb, 256>>>(pos, batch, ei);
    kCenterScan<<<NBLK, 256>>>(pos, batch);
    kScanB<<<1, 512>>>();
    kScanC<<<NBLK, 256>>>();
    kEdgeFill<<<eb, 256>>>(ei);
    for (int l = 0; l < 3; l++) {
        kNodeFuse<<<nb, 256>>>(wse, bse, Wemb, Wmix, Wgate, bgate, Ws1, l);
        kEdgeLayerC<<<NE / 128, 128>>>(Wg, bg, Ws1, bs1, l);
    }
    kOut<<<nb, 256>>>(W1, b1, W2, b2, batch, out);
}

// round 13
// speedup vs baseline: 1.0326x; 1.0326x over previous
#include <cuda_runtime.h>
#include <math.h>

#define NN 100000
#define NE 1600000
#define NG 1000
#define NBLK 391   // ceil(NN/256)
#define SLOT 33
typedef unsigned long long ull;

// ---- scratch (static device globals; no allocation) ----
__device__ __align__(128) float g_posg[NN * 2];
__device__ __align__(128) float g_ncs [NN * 2];
__device__ __align__(128) float g_nacc[NN * 4];
__device__ __align__(128) float g_gacc[NG * 4];
__device__ int   g_deg[NN];
__device__ int   g_rowstart[NN];
__device__ int   g_cursor[NN];
__device__ int   g_psum[512];
__device__ __align__(128) float4 g_rec[NE];   // col(bits), s1*invd, c1, s1*(d+eps)/sqrt2
__device__ int   g_erow[NE];
__device__ __align__(128) float g_xs  [NN * 16];
__device__ __align__(128) float g_xrot[NN * 32];
__device__ __align__(128) float g_y   [NN * 32];
__device__ __align__(128) float g_as  [NN * 16];
__device__ __align__(128) float g_gate[NN * 16];
__device__ __align__(128) float g_aggR[NN * 32];
__device__ __align__(128) float g_aggS[NN * 16];

__device__ __forceinline__ void red4(float* a, float x, float y, float z, float w) {
    asm volatile("red.global.add.v4.f32 [%0], {%1,%2,%3,%4};"
                 :: "l"(a), "f"(x), "f"(y), "f"(z), "f"(w));
}
__device__ __forceinline__ void red1(float* a, float v) {
    asm volatile("red.global.add.f32 [%0], %1;" :: "l"(a), "f"(v));
}
__device__ __forceinline__ float lrelu(float x) { return x > 0.f ? x : 0.01f * x; }
__device__ __forceinline__ ull fma2(ull a, ull b, ull c) {
    ull d; asm("fma.rn.f32x2 %0,%1,%2,%3;" : "=l"(d) : "l"(a), "l"(b), "l"(c)); return d;
}
__device__ __forceinline__ ull pk2(float x, float y) {
    ull r; asm("mov.b64 %0,{%1,%2};" : "=l"(r) : "f"(x), "f"(y)); return r;
}
__device__ __forceinline__ float2 upk(ull v) {
    float2 r; asm("mov.b64 {%0,%1},%2;" : "=f"(r.x), "=f"(r.y) : "l"(v)); return r;
}

// ---- zero ----
__global__ void kZero(float* out) {
    int i = blockIdx.x * blockDim.x + threadIdx.x;
    for (int t = i; t < NN * 4; t += gridDim.x * blockDim.x) g_nacc[t] = 0.f;
    for (int t = i; t < NN; t += gridDim.x * blockDim.x) g_deg[t] = 0;
    if (i < NG * 4) g_gacc[i] = 0.f;
    if (i < NG * 6) out[i] = 0.f;
}

// edge-grid: per-edge degree histogram; first NN threads also do graph mean acc
__global__ void kGraphAcc(const float* __restrict__ pos, const int* __restrict__ batch,
                          const int* __restrict__ ei) {
    int n = blockIdx.x * blockDim.x + threadIdx.x;
    if (n < NN)
        red4(&g_gacc[batch[n] * 4], pos[2 * n], pos[2 * n + 1], 1.f, 0.f);
    if (n < NE)
        atomicAdd(&g_deg[ei[n]], 1);
}

// fused: center/rot (independent) + block-local scan of degrees
__global__ void kCenterScan(const float* __restrict__ pos, const int* __restrict__ batch) {
    __shared__ int s[256];
    int n = blockIdx.x * 256 + threadIdx.x;
    int v = (n < NN) ? g_deg[n] : 0;
    s[threadIdx.x] = v; __syncthreads();
    for (int d = 1; d < 256; d <<= 1) {
        int t = (threadIdx.x >= d) ? s[threadIdx.x - d] : 0;
        __syncthreads();
        s[threadIdx.x] += t;
        __syncthreads();
    }
    if (n < NN) g_rowstart[n] = s[threadIdx.x] - v;
    if (threadIdx.x == 255) g_psum[blockIdx.x] = s[255];
    if (n >= NN) return;
    float4 ga = *(const float4*)&g_gacc[batch[n] * 4];
    float inv = 1.f / fmaxf(ga.z, 1.f);
    float px = pos[2 * n]     - ga.x * inv;
    float py = pos[2 * n + 1] - ga.y * inv;
    g_posg[2 * n] = px; g_posg[2 * n + 1] = py;
    float r2 = px * px + py * py;
    float c = 1.f, sv = 0.f;
    if (r2 > 0.f) { float ir = rsqrtf(r2); c = px * ir; sv = py * ir; }
    g_ncs[2 * n] = c; g_ncs[2 * n + 1] = sv;
}

__global__ void kScanB() {
    __shared__ int s[512];
    int t = threadIdx.x;
    int v = (t < NBLK) ? g_psum[t] : 0;
    s[t] = v; __syncthreads();
    for (int d = 1; d < 512; d <<= 1) {
        int u = (t >= d) ? s[t - d] : 0;
        __syncthreads();
        s[t] += u;
        __syncthreads();
    }
    if (t < NBLK) g_psum[t] = s[t] - v;
}

__global__ void kScanC() {
    int n = blockIdx.x * 256 + threadIdx.x;
    if (n >= NN) return;
    int rs = g_rowstart[n] + g_psum[blockIdx.x];
    g_rowstart[n] = rs;
    g_cursor[n] = rs;
}

// ---- per-edge geometry + CSR fill ----
__global__ void kEdgeFill(const int* __restrict__ ei) {
    int e = blockIdx.x * blockDim.x + threadIdx.x;
    if (e >= NE) return;
    int r = ei[e], c = ei[NE + e];
    float vx = g_posg[2 * r] - g_posg[2 * c];
    float vy = g_posg[2 * r + 1] - g_posg[2 * c + 1];
    float r2 = vx * vx + vy * vy;
    float d = 0.f, cc = 1.f, ss = 0.f;
    if (r2 > 0.f) { float ir = rsqrtf(r2); d = r2 * ir; cc = vx * ir; ss = vy * ir; }
    float invd = 1.41421356237f / (d + 1e-8f);
    float s1, c1;
    __sincosf(3.14159265358979f * d, &s1, &c1);
    int pos = atomicAdd(&g_cursor[r], 1);
    g_rec[pos] = make_float4(__int_as_float(c), s1 * invd, c1,
                             s1 * (d + 1e-8f) * 0.70710678118f);
    g_erow[pos] = r;
    red4(&g_nacc[r * 4], 1.f, d, cc, ss);
}

// ---- fused node kernel: post(prev) / init + pre(layer); zero agg ----
__global__ void kNodeFuse(const float* __restrict__ wse, const float* __restrict__ bse,
                          const float* __restrict__ Wemb,
                          const float* __restrict__ Wmix, const float* __restrict__ Wgate,
                          const float* __restrict__ bgate, const float* __restrict__ Ws1,
                          int layer) {
    __shared__ __align__(16) ull sMix2[256];   // Wmix[i][j] duplicated into both halves
    __shared__ __align__(16) ull sGate2[128], sWs2[128];
    __shared__ ull sbg2[8];
    for (int t = threadIdx.x; t < 256; t += blockDim.x) {
        float w = Wmix[layer * 256 + t];
        sMix2[t] = pk2(w, w);
    }
    for (int t = threadIdx.x; t < 128; t += blockDim.x) {
        sGate2[t] = ((const ull*)(Wgate + layer * 256))[t];
        sWs2[t]   = ((const ull*)(Ws1 + layer * 512))[t];
    }
    if (threadIdx.x < 8) sbg2[threadIdx.x] = ((const ull*)(bgate + layer * 16))[threadIdx.x];
    __syncthreads();
    int n = blockIdx.x * blockDim.x + threadIdx.x;
    if (n >= NN) return;

    float xs[16], xr[32];
    if (layer == 0) {
        float4 a = *(const float4*)&g_nacc[n * 4];
        float deg = fmaxf(a.x, 1.f);
        float invdeg = 1.f / deg;
        float dmean = a.y * invdeg;
        float Cm = a.z * invdeg, Sm = a.w * invdeg;
#pragma unroll
        for (int i = 0; i < 16; i++) xs[i] = lrelu(dmean * wse[i] + bse[i]);
#pragma unroll
        for (int j = 0; j < 16; j++) {
            float w0 = Wemb[2 * j], w1 = Wemb[2 * j + 1];
            xr[2 * j]     = Cm * w0 - Sm * w1;
            xr[2 * j + 1] = Sm * w0 + Cm * w1;
        }
        g_nacc[n * 4] = invdeg;
        float4* po = (float4*)&g_xs[n * 16];
#pragma unroll
        for (int q = 0; q < 4; q++) po[q] = make_float4(xs[4*q], xs[4*q+1], xs[4*q+2], xs[4*q+3]);
        float4* pr = (float4*)&g_xrot[n * 32];
#pragma unroll
        for (int q = 0; q < 8; q++) pr[q] = make_float4(xr[4*q], xr[4*q+1], xr[4*q+2], xr[4*q+3]);
    } else {
        const float4* p = (const float4*)&g_xs[n * 16];
#pragma unroll
        for (int q = 0; q < 4; q++) { float4 v = p[q]; xs[4*q]=v.x; xs[4*q+1]=v.y; xs[4*q+2]=v.z; xs[4*q+3]=v.w; }
        const float4* pr = (const float4*)&g_xrot[n * 32];
#pragma unroll
        for (int q = 0; q < 8; q++) { float4 v = pr[q]; xr[4*q]=v.x; xr[4*q+1]=v.y; xr[4*q+2]=v.z; xr[4*q+3]=v.w; }
        float invd = g_nacc[n * 4];
#pragma unroll
        for (int j = 0; j < 16; j++) {
            float gt = g_gate[n * 16 + j] * invd;
            xr[2 * j]     += gt * g_aggR[n * 32 + 2 * j];
            xr[2 * j + 1] += gt * g_aggR[n * 32 + 2 * j + 1];
        }
#pragma unroll
        for (int i = 0; i < 16; i++) xs[i] += g_aggS[n * 16 + i] * invd;
        float4* po = (float4*)&g_xs[n * 16];
#pragma unroll
        for (int q = 0; q < 4; q++) po[q] = make_float4(xs[4*q], xs[4*q+1], xs[4*q+2], xs[4*q+3]);
        float4* pw = (float4*)&g_xrot[n * 32];
#pragma unroll
        for (int q = 0; q < 8; q++) pw[q] = make_float4(xr[4*q], xr[4*q+1], xr[4*q+2], xr[4*q+3]);
    }

    // y = Wmix @ x_rot  (packed, vectorized weight loads)
    ull xr2[16];
#pragma unroll
    for (int j = 0; j < 16; j++) xr2[j] = pk2(xr[2 * j], xr[2 * j + 1]);
    ull* yo2 = (ull*)&g_y[n * 32];
#pragma unroll
    for (int i = 0; i < 16; i++) {
        ull acc = 0ull;
        const ulonglong2* wm = (const ulonglong2*)(sMix2 + i * 16);
#pragma unroll
        for (int j = 0; j < 8; j++) {
            ulonglong2 wp = wm[j];
            acc = fma2(wp.x, xr2[2 * j], acc);
            acc = fma2(wp.y, xr2[2 * j + 1], acc);
        }
        yo2[i] = acc;
    }
    ull gt2[8], as2[8];
#pragma unroll
    for (int i = 0; i < 8; i++) { gt2[i] = sbg2[i]; as2[i] = 0ull; }
#pragma unroll
    for (int k = 0; k < 16; k++) {
        ull xv2 = pk2(xs[k], xs[k]);
        const ulonglong2* wg = (const ulonglong2*)(sGate2 + k * 8);
        const ulonglong2* ws = (const ulonglong2*)(sWs2 + k * 8);
#pragma unroll
        for (int i = 0; i < 4; i++) {
            ulonglong2 wgp = wg[i], wsp = ws[i];
            gt2[2 * i]     = fma2(xv2, wgp.x, gt2[2 * i]);
            gt2[2 * i + 1] = fma2(xv2, wgp.y, gt2[2 * i + 1]);
            as2[2 * i]     = fma2(xv2, wsp.x, as2[2 * i]);
            as2[2 * i + 1] = fma2(xv2, wsp.y, as2[2 * i + 1]);
        }
    }
#pragma unroll
    for (int i = 0; i < 8; i++) {
        float2 gv = upk(gt2[i]);
        g_gate[n * 16 + 2 * i]     = 1.f / (1.f + __expf(-gv.x));
        g_gate[n * 16 + 2 * i + 1] = 1.f / (1.f + __expf(-gv.y));
        ((ull*)&g_as[n * 16])[i] = as2[i];
    }
    // zero accumulators for this layer's edge pass
    float4 z = make_float4(0.f, 0.f, 0.f, 0.f);
    float4* ar = (float4*)&g_aggR[n * 32];
#pragma unroll
    for (int q = 0; q < 8; q++) ar[q] = z;
    float4* as4 = (float4*)&g_aggS[n * 16];
#pragma unroll
    for (int q = 0; q < 4; q++) as4[q] = z;
}

// ---- per-edge layer (hot): warp = 32 CSR edges; R11 structure + bounded mid-phase prefetch ----
__global__ void __launch_bounds__(128) kEdgeLayerC(
                           const float* __restrict__ Wg, const float* __restrict__ bg,
                           const float* __restrict__ Ws1, const float* __restrict__ bs1,
                           int layer) {
    __shared__ __align__(16) ull sWg2[128], sWs2[128];
    __shared__ ull sbg2[8], sbs2[8];
    __shared__ float smG[4][32 * SLOT];
    __shared__ int scol[4][32], srow[4][32];
    for (int t = threadIdx.x; t < 128; t += blockDim.x) {
        sWg2[t] = ((const ull*)(Wg + layer * 256))[t];
        sWs2[t] = ((const ull*)(Ws1 + layer * 512 + 256))[t];
    }
    if (threadIdx.x < 8) {
        sbg2[threadIdx.x] = ((const ull*)(bg + layer * 16))[threadIdx.x];
        sbs2[threadIdx.x] = ((const ull*)(bs1 + layer * 16))[threadIdx.x];
    }
    __syncthreads();
    int w = threadIdx.x >> 5;
    int lane = threadIdx.x & 31;
    int p = blockIdx.x * 128 + threadIdx.x;   // NE % 128 == 0
    bool sl = (lane < 16);

    float4 rec = g_rec[p];
    scol[w][lane] = __float_as_int(rec.x);
    srow[w][lane] = g_erow[p];
    __syncwarp();

    // ---- phase 1a: bessel + g-pass ----
    float emb[16];
    {
        float s1p = rec.y, c1 = rec.z, t1 = rec.w;
        emb[0] = s1p;
        float sk = s1p, ck = c1;
#pragma unroll
        for (int k = 1; k < 16; k++) {
            float sn = fmaf(sk, c1,  ck * s1p);
            float cn = fmaf(ck, c1, -sk * t1);
            emb[k] = sn; sk = sn; ck = cn;
        }
    }
    float* slot = &smG[w][lane * SLOT];
    {
        ull g2[8];
#pragma unroll
        for (int i = 0; i < 8; i++) g2[i] = sbg2[i];
#pragma unroll
        for (int k = 0; k < 16; k++) {
            ull dv2 = pk2(emb[k], emb[k]);
            const ulonglong2* wg = (const ulonglong2*)(sWg2 + k * 8);
#pragma unroll
            for (int i = 0; i < 4; i++) {
                ulonglong2 wgp = wg[i];
                g2[2 * i]     = fma2(dv2, wgp.x, g2[2 * i]);
                g2[2 * i + 1] = fma2(dv2, wgp.y, g2[2 * i + 1]);
            }
        }
#pragma unroll
        for (int i = 0; i < 8; i++) {
            float2 gv = upk(g2[i]);
            slot[2 * i]     = gv.x;
            slot[2 * i + 1] = gv.y;
        }
    }

    // ---- bounded prefetch of half-0 gathers (g-pass accumulators now dead) ----
    const int* colw = scol[w];
    const int* roww = srow[w];
    float yv[16], av[16];
#pragma unroll
    for (int e = 0; e < 16; e++) {
        int c = colw[e];
        yv[e] = g_y[(size_t)c * 32 + lane];
        av[e] = sl ? g_as[(size_t)c * 16 + lane] : 0.f;
    }

    // ---- phase 1b: bs-pass (inside gather latency shadow) ----
    {
        ull b2[8];
#pragma unroll
        for (int i = 0; i < 8; i++) b2[i] = sbs2[i];
#pragma unroll
        for (int k = 0; k < 16; k++) {
            ull dv2 = pk2(emb[k], emb[k]);
            const ulonglong2* ws = (const ulonglong2*)(sWs2 + k * 8);
#pragma unroll
            for (int i = 0; i < 4; i++) {
                ulonglong2 wsp = ws[i];
                b2[2 * i]     = fma2(dv2, wsp.x, b2[2 * i]);
                b2[2 * i + 1] = fma2(dv2, wsp.y, b2[2 * i + 1]);
            }
        }
#pragma unroll
        for (int i = 0; i < 8; i++) {
            float2 bv = upk(b2[i]);
            slot[16 + 2 * i]     = bv.x;
            slot[16 + 2 * i + 1] = bv.y;
        }
    }
    __syncwarp();

    // ---- phase 2: accumulate half 0 (prefetched), prefetch+accumulate half 1 ----
    const float* smw = smG[w];
    int gidx = lane >> 1;
    float accR = 0.f, accS = 0.f;
    int cur = roww[0];
#pragma unroll
    for (int e = 0; e < 16; e++) {
        int r = roww[e];
        if (r != cur) {
            red1(&g_aggR[(size_t)cur * 32 + lane], accR);
            if (sl) red1(&g_aggS[(size_t)cur * 16 + lane], accS);
            accR = 0.f; accS = 0.f; cur = r;
        }
        float gv = smw[e * SLOT + gidx];
        accR = fmaf(gv, yv[e], accR);
        if (sl) accS += lrelu(av[e] + smw[e * SLOT + 16 + lane]);
    }
#pragma unroll
    for (int e = 0; e < 16; e++) {
        int c = colw[16 + e];
        yv[e] = g_y[(size_t)c * 32 + lane];
        av[e] = sl ? g_as[(size_t)c * 16 + lane] : 0.f;
    }
#pragma unroll
    for (int e = 16; e < 32; e++) {
        int r = roww[e];
        if (r != cur) {
            red1(&g_aggR[(size_t)cur * 32 + lane], accR);
            if (sl) red1(&g_aggS[(size_t)cur * 16 + lane], accS);
            accR = 0.f; accS = 0.f; cur = r;
        }
        float gv = smw[e * SLOT + gidx];
        accR = fmaf(gv, yv[e - 16], accR);
        if (sl) accS += lrelu(av[e - 16] + smw[e * SLOT + 16 + lane]);
    }
    red1(&g_aggR[(size_t)cur * 32 + lane], accR);
    if (sl) red1(&g_aggS[(size_t)cur * 16 + lane], accS);
}

// ---- readout: final post + rotate out + 48->144->6 MLP (f32x2) + graph scatter ----
__global__ void __launch_bounds__(256) kOut(
                     const float* __restrict__ W1, const float* __restrict__ b1,
                     const float* __restrict__ W2, const float* __restrict__ b2,
                     const int* __restrict__ batch, float* __restrict__ out) {
    __shared__ __align__(16) float sW1[48 * 144];
    __shared__ __align__(16) float sW2[144 * 6];
    __shared__ __align__(16) float sb1[144];
    __shared__ float sb2[8];
    for (int t = threadIdx.x; t < 48 * 144; t += blockDim.x) sW1[t] = W1[t];
    for (int t = threadIdx.x; t < 144 * 6; t += blockDim.x) sW2[t] = W2[t];
    for (int t = threadIdx.x; t < 144; t += blockDim.x) sb1[t] = b1[t];
    if (threadIdx.x < 6) sb2[threadIdx.x] = b2[threadIdx.x];
    if (threadIdx.x >= 6 && threadIdx.x < 8) sb2[threadIdx.x] = 0.f;
    __syncthreads();
    int n = blockIdx.x * blockDim.x + threadIdx.x;
    if (n >= NN) return;
    float invd = g_nacc[n * 4];
    float xc[48];
#pragma unroll
    for (int i = 0; i < 16; i++)
        xc[i] = g_xs[n * 16 + i] + g_aggS[n * 16 + i] * invd;
    float cc = g_ncs[2 * n], ss = g_ncs[2 * n + 1];
#pragma unroll
    for (int j = 0; j < 16; j++) {
        float gt = g_gate[n * 16 + j] * invd;
        float x0 = g_xrot[n * 32 + 2 * j]     + gt * g_aggR[n * 32 + 2 * j];
        float x1 = g_xrot[n * 32 + 2 * j + 1] + gt * g_aggR[n * 32 + 2 * j + 1];
        xc[16 + 2 * j]     = cc * x0 - ss * x1;
        xc[16 + 2 * j + 1] = ss * x0 + cc * x1;
    }
    ull u2[3];
    u2[0] = pk2(sb2[0], sb2[1]);
    u2[1] = pk2(sb2[2], sb2[3]);
    u2[2] = pk2(sb2[4], sb2[5]);
    for (int o = 0; o < 144; o += 4) {
        const ull* wb = (const ull*)&sb1[o];
        ull h01 = wb[0], h23 = wb[1];
#pragma unroll
        for (int k = 0; k < 48; k++) {
            const ull* wp = (const ull*)&sW1[k * 144 + o];
            ull xv2 = pk2(xc[k], xc[k]);
            h01 = fma2(xv2, wp[0], h01);
            h23 = fma2(xv2, wp[1], h23);
        }
        float2 ha = upk(h01), hb = upk(h23);
        float hv[4] = {lrelu(ha.x), lrelu(ha.y), lrelu(hb.x), lrelu(hb.y)};
#pragma unroll
        for (int j = 0; j < 4; j++) {
            ull hj2 = pk2(hv[j], hv[j]);
            const ull* w2p = (const ull*)&sW2[(o + j) * 6];
            u2[0] = fma2(hj2, w2p[0], u2[0]);
            u2[1] = fma2(hj2, w2p[1], u2[1]);
            u2[2] = fma2(hj2, w2p[2], u2[2]);
        }
    }
    int b = batch[n];
    float2 ua = upk(u2[0]), ub = upk(u2[1]), uc = upk(u2[2]);
    atomicAdd(&out[b * 6 + 0], ua.x);
    atomicAdd(&out[b * 6 + 1], ua.y);
    atomicAdd(&out[b * 6 + 2], ub.x);
    atomicAdd(&out[b * 6 + 3], ub.y);
    atomicAdd(&out[b * 6 + 4], uc.x);
    atomicAdd(&out[b * 6 + 5], uc.y);
}

extern "C" void kernel_launch(void* const* d_in, const int* in_sizes, int n_in,
                              void* d_out, int out_size) {
    const float* pos   = (const float*)d_in[0];
    const float* Wemb  = (const float*)d_in[1];
    const float* wse   = (const float*)d_in[2];
    const float* bse   = (const float*)d_in[3];
    const float* Wg    = (const float*)d_in[4];
    const float* bg    = (const float*)d_in[5];
    const float* Wmix  = (const float*)d_in[6];
    const float* Wgate = (const float*)d_in[7];
    const float* bgate = (const float*)d_in[8];
    const float* Ws1   = (const float*)d_in[9];
    const float* bs1   = (const float*)d_in[10];
    const float* W1    = (const float*)d_in[11];
    const float* b1    = (const float*)d_in[12];
    const float* W2    = (const float*)d_in[13];
    const float* b2    = (const float*)d_in[14];
    const int*   ei    = (const int*)d_in[15];
    const int*   batch = (const int*)d_in[16];
    float* out = (float*)d_out;

    int nb = (NN + 255) / 256;
    int eb = (NE + 255) / 256;

    kZero<<<1563, 256>>>(out);
    kGraphAcc<<<eb, 256>>>(pos, batch, ei);
    kCenterScan<<<NBLK, 256>>>(pos, batch);
    kScanB<<<1, 512>>>();
    kScanC<<<NBLK, 256>>>();
    kEdgeFill<<<eb, 256>>>(ei);
    for (int l = 0; l < 3; l++) {
        kNodeFuse<<<nb, 256>>>(wse, bse, Wemb, Wmix, Wgate, bgate, Ws1, l);
        kEdgeLayerC<<<NE / 128, 128>>>(Wg, bg, Ws1, bs1, l);
    }
    kOut<<<nb, 256>>>(W1, b1, W2, b2, batch, out);
}

// round 14
// speedup vs baseline: 1.0710x; 1.0371x over previous
#include <cuda_runtime.h>
#include <math.h>

#define NN 100000
#define NE 1600000
#define NG 1000
#define NBLK 391   // ceil(NN/256)
#define SLOT 33
typedef unsigned long long ull;

// ---- scratch (static device globals; no allocation) ----
__device__ __align__(128) float g_posg[NN * 2];
__device__ __align__(128) float g_ncs [NN * 2];
__device__ __align__(128) float g_nacc[NN * 4];
__device__ __align__(128) float g_gacc[NG * 4];
__device__ int   g_deg[NN];
__device__ int   g_rowstart[NN];
__device__ int   g_cursor[NN];
__device__ int   g_psum[512];
__device__ __align__(128) float4 g_rec[NE];   // col(bits), s1*invd, c1, s1*(d+eps)/sqrt2
__device__ int   g_erow[NE];
__device__ __align__(128) float g_xs  [NN * 16];
__device__ __align__(128) float g_xrot[NN * 32];
__device__ __align__(128) float g_y   [NN * 32];
__device__ __align__(128) float g_as  [NN * 16];
__device__ __align__(128) float g_gate[NN * 16];
__device__ __align__(128) float g_aggR[NN * 32];
__device__ __align__(128) float g_aggS[NN * 16];

__device__ __forceinline__ void red4(float* a, float x, float y, float z, float w) {
    asm volatile("red.global.add.v4.f32 [%0], {%1,%2,%3,%4};"
                 :: "l"(a), "f"(x), "f"(y), "f"(z), "f"(w));
}
__device__ __forceinline__ void red1(float* a, float v) {
    asm volatile("red.global.add.f32 [%0], %1;" :: "l"(a), "f"(v));
}
__device__ __forceinline__ float lrelu(float x) { return x > 0.f ? x : 0.01f * x; }
__device__ __forceinline__ ull fma2(ull a, ull b, ull c) {
    ull d; asm("fma.rn.f32x2 %0,%1,%2,%3;" : "=l"(d) : "l"(a), "l"(b), "l"(c)); return d;
}
__device__ __forceinline__ ull pk2(float x, float y) {
    ull r; asm("mov.b64 %0,{%1,%2};" : "=l"(r) : "f"(x), "f"(y)); return r;
}
__device__ __forceinline__ float2 upk(ull v) {
    float2 r; asm("mov.b64 {%0,%1},%2;" : "=f"(r.x), "=f"(r.y) : "l"(v)); return r;
}

// ---- zero ----
__global__ void kZero(float* out) {
    int i = blockIdx.x * blockDim.x + threadIdx.x;
    for (int t = i; t < NN * 4; t += gridDim.x * blockDim.x) g_nacc[t] = 0.f;
    for (int t = i; t < NN; t += gridDim.x * blockDim.x) g_deg[t] = 0;
    if (i < NG * 4) g_gacc[i] = 0.f;
    if (i < NG * 6) out[i] = 0.f;
}

// edge-grid: per-edge degree histogram; first NN threads also do graph mean acc
__global__ void kGraphAcc(const float* __restrict__ pos, const int* __restrict__ batch,
                          const int* __restrict__ ei) {
    int n = blockIdx.x * blockDim.x + threadIdx.x;
    if (n < NN)
        red4(&g_gacc[batch[n] * 4], pos[2 * n], pos[2 * n + 1], 1.f, 0.f);
    if (n < NE)
        atomicAdd(&g_deg[ei[n]], 1);
}

// fused: center/rot (independent) + block-local scan of degrees
__global__ void kCenterScan(const float* __restrict__ pos, const int* __restrict__ batch) {
    __shared__ int s[256];
    int n = blockIdx.x * 256 + threadIdx.x;
    int v = (n < NN) ? g_deg[n] : 0;
    s[threadIdx.x] = v; __syncthreads();
    for (int d = 1; d < 256; d <<= 1) {
        int t = (threadIdx.x >= d) ? s[threadIdx.x - d] : 0;
        __syncthreads();
        s[threadIdx.x] += t;
        __syncthreads();
    }
    if (n < NN) g_rowstart[n] = s[threadIdx.x] - v;
    if (threadIdx.x == 255) g_psum[blockIdx.x] = s[255];
    if (n >= NN) return;
    float4 ga = *(const float4*)&g_gacc[batch[n] * 4];
    float inv = 1.f / fmaxf(ga.z, 1.f);
    float px = pos[2 * n]     - ga.x * inv;
    float py = pos[2 * n + 1] - ga.y * inv;
    g_posg[2 * n] = px; g_posg[2 * n + 1] = py;
    float r2 = px * px + py * py;
    float c = 1.f, sv = 0.f;
    if (r2 > 0.f) { float ir = rsqrtf(r2); c = px * ir; sv = py * ir; }
    g_ncs[2 * n] = c; g_ncs[2 * n + 1] = sv;
}

__global__ void kScanB() {
    __shared__ int s[512];
    int t = threadIdx.x;
    int v = (t < NBLK) ? g_psum[t] : 0;
    s[t] = v; __syncthreads();
    for (int d = 1; d < 512; d <<= 1) {
        int u = (t >= d) ? s[t - d] : 0;
        __syncthreads();
        s[t] += u;
        __syncthreads();
    }
    if (t < NBLK) g_psum[t] = s[t] - v;
}

__global__ void kScanC() {
    int n = blockIdx.x * 256 + threadIdx.x;
    if (n >= NN) return;
    int rs = g_rowstart[n] + g_psum[blockIdx.x];
    g_rowstart[n] = rs;
    g_cursor[n] = rs;
}

// ---- per-edge geometry + CSR fill ----
__global__ void kEdgeFill(const int* __restrict__ ei) {
    int e = blockIdx.x * blockDim.x + threadIdx.x;
    if (e >= NE) return;
    int r = ei[e], c = ei[NE + e];
    float vx = g_posg[2 * r] - g_posg[2 * c];
    float vy = g_posg[2 * r + 1] - g_posg[2 * c + 1];
    float r2 = vx * vx + vy * vy;
    float d = 0.f, cc = 1.f, ss = 0.f;
    if (r2 > 0.f) { float ir = rsqrtf(r2); d = r2 * ir; cc = vx * ir; ss = vy * ir; }
    float invd = 1.41421356237f / (d + 1e-8f);
    float s1, c1;
    __sincosf(3.14159265358979f * d, &s1, &c1);
    int pos = atomicAdd(&g_cursor[r], 1);
    g_rec[pos] = make_float4(__int_as_float(c), s1 * invd, c1,
                             s1 * (d + 1e-8f) * 0.70710678118f);
    g_erow[pos] = r;
    red4(&g_nacc[r * 4], 1.f, d, cc, ss);
}

// ---- fused node kernel: post(prev) / init + pre(layer); zero agg ----
__global__ void kNodeFuse(const float* __restrict__ wse, const float* __restrict__ bse,
                          const float* __restrict__ Wemb,
                          const float* __restrict__ Wmix, const float* __restrict__ Wgate,
                          const float* __restrict__ bgate, const float* __restrict__ Ws1,
                          int layer) {
    __shared__ __align__(16) ull sMix2[256];   // Wmix[i][j] duplicated into both halves
    __shared__ __align__(16) ull sGate2[128], sWs2[128];
    __shared__ ull sbg2[8];
    for (int t = threadIdx.x; t < 256; t += blockDim.x) {
        float w = Wmix[layer * 256 + t];
        sMix2[t] = pk2(w, w);
    }
    for (int t = threadIdx.x; t < 128; t += blockDim.x) {
        sGate2[t] = ((const ull*)(Wgate + layer * 256))[t];
        sWs2[t]   = ((const ull*)(Ws1 + layer * 512))[t];
    }
    if (threadIdx.x < 8) sbg2[threadIdx.x] = ((const ull*)(bgate + layer * 16))[threadIdx.x];
    __syncthreads();
    int n = blockIdx.x * blockDim.x + threadIdx.x;
    if (n >= NN) return;

    float xs[16], xr[32];
    if (layer == 0) {
        float4 a = *(const float4*)&g_nacc[n * 4];
        float deg = fmaxf(a.x, 1.f);
        float invdeg = 1.f / deg;
        float dmean = a.y * invdeg;
        float Cm = a.z * invdeg, Sm = a.w * invdeg;
#pragma unroll
        for (int i = 0; i < 16; i++) xs[i] = lrelu(dmean * wse[i] + bse[i]);
#pragma unroll
        for (int j = 0; j < 16; j++) {
            float w0 = Wemb[2 * j], w1 = Wemb[2 * j + 1];
            xr[2 * j]     = Cm * w0 - Sm * w1;
            xr[2 * j + 1] = Sm * w0 + Cm * w1;
        }
        g_nacc[n * 4] = invdeg;
        float4* po = (float4*)&g_xs[n * 16];
#pragma unroll
        for (int q = 0; q < 4; q++) po[q] = make_float4(xs[4*q], xs[4*q+1], xs[4*q+2], xs[4*q+3]);
        float4* pr = (float4*)&g_xrot[n * 32];
#pragma unroll
        for (int q = 0; q < 8; q++) pr[q] = make_float4(xr[4*q], xr[4*q+1], xr[4*q+2], xr[4*q+3]);
    } else {
        const float4* p = (const float4*)&g_xs[n * 16];
#pragma unroll
        for (int q = 0; q < 4; q++) { float4 v = p[q]; xs[4*q]=v.x; xs[4*q+1]=v.y; xs[4*q+2]=v.z; xs[4*q+3]=v.w; }
        const float4* pr = (const float4*)&g_xrot[n * 32];
#pragma unroll
        for (int q = 0; q < 8; q++) { float4 v = pr[q]; xr[4*q]=v.x; xr[4*q+1]=v.y; xr[4*q+2]=v.z; xr[4*q+3]=v.w; }
        float invd = g_nacc[n * 4];
#pragma unroll
        for (int j = 0; j < 16; j++) {
            float gt = g_gate[n * 16 + j] * invd;
            xr[2 * j]     += gt * g_aggR[n * 32 + 2 * j];
            xr[2 * j + 1] += gt * g_aggR[n * 32 + 2 * j + 1];
        }
#pragma unroll
        for (int i = 0; i < 16; i++) xs[i] += g_aggS[n * 16 + i] * invd;
        float4* po = (float4*)&g_xs[n * 16];
#pragma unroll
        for (int q = 0; q < 4; q++) po[q] = make_float4(xs[4*q], xs[4*q+1], xs[4*q+2], xs[4*q+3]);
        float4* pw = (float4*)&g_xrot[n * 32];
#pragma unroll
        for (int q = 0; q < 8; q++) pw[q] = make_float4(xr[4*q], xr[4*q+1], xr[4*q+2], xr[4*q+3]);
    }

    // y = Wmix @ x_rot  (packed, vectorized weight loads)
    ull xr2[16];
#pragma unroll
    for (int j = 0; j < 16; j++) xr2[j] = pk2(xr[2 * j], xr[2 * j + 1]);
    ull* yo2 = (ull*)&g_y[n * 32];
#pragma unroll
    for (int i = 0; i < 16; i++) {
        ull acc = 0ull;
        const ulonglong2* wm = (const ulonglong2*)(sMix2 + i * 16);
#pragma unroll
        for (int j = 0; j < 8; j++) {
            ulonglong2 wp = wm[j];
            acc = fma2(wp.x, xr2[2 * j], acc);
            acc = fma2(wp.y, xr2[2 * j + 1], acc);
        }
        yo2[i] = acc;
    }
    ull gt2[8], as2[8];
#pragma unroll
    for (int i = 0; i < 8; i++) { gt2[i] = sbg2[i]; as2[i] = 0ull; }
#pragma unroll
    for (int k = 0; k < 16; k++) {
        ull xv2 = pk2(xs[k], xs[k]);
        const ulonglong2* wg = (const ulonglong2*)(sGate2 + k * 8);
        const ulonglong2* ws = (const ulonglong2*)(sWs2 + k * 8);
#pragma unroll
        for (int i = 0; i < 4; i++) {
            ulonglong2 wgp = wg[i], wsp = ws[i];
            gt2[2 * i]     = fma2(xv2, wgp.x, gt2[2 * i]);
            gt2[2 * i + 1] = fma2(xv2, wgp.y, gt2[2 * i + 1]);
            as2[2 * i]     = fma2(xv2, wsp.x, as2[2 * i]);
            as2[2 * i + 1] = fma2(xv2, wsp.y, as2[2 * i + 1]);
        }
    }
#pragma unroll
    for (int i = 0; i < 8; i++) {
        float2 gv = upk(gt2[i]);
        g_gate[n * 16 + 2 * i]     = 1.f / (1.f + __expf(-gv.x));
        g_gate[n * 16 + 2 * i + 1] = 1.f / (1.f + __expf(-gv.y));
        ((ull*)&g_as[n * 16])[i] = as2[i];
    }
    // zero accumulators for this layer's edge pass
    float4 z = make_float4(0.f, 0.f, 0.f, 0.f);
    float4* ar = (float4*)&g_aggR[n * 32];
#pragma unroll
    for (int q = 0; q < 8; q++) ar[q] = z;
    float4* as4 = (float4*)&g_aggS[n * 16];
#pragma unroll
    for (int q = 0; q < 4; q++) as4[q] = z;
}

// ---- per-edge layer (hot): warp = 32 CSR edges; R11 structure; occupancy-boosted ----
__global__ void __launch_bounds__(128, 7) kEdgeLayerC(
                           const float* __restrict__ Wg, const float* __restrict__ bg,
                           const float* __restrict__ Ws1, const float* __restrict__ bs1,
                           int layer) {
    __shared__ __align__(16) ull sWg2[128], sWs2[128];
    __shared__ ull sbg2[8], sbs2[8];
    __shared__ float smG[4][32 * SLOT];
    __shared__ int scol[4][32], srow[4][32];
    for (int t = threadIdx.x; t < 128; t += blockDim.x) {
        sWg2[t] = ((const ull*)(Wg + layer * 256))[t];
        sWs2[t] = ((const ull*)(Ws1 + layer * 512 + 256))[t];
    }
    if (threadIdx.x < 8) {
        sbg2[threadIdx.x] = ((const ull*)(bg + layer * 16))[threadIdx.x];
        sbs2[threadIdx.x] = ((const ull*)(bs1 + layer * 16))[threadIdx.x];
    }
    __syncthreads();
    int w = threadIdx.x >> 5;
    int lane = threadIdx.x & 31;
    int p = blockIdx.x * 128 + threadIdx.x;   // NE % 128 == 0
    bool sl = (lane < 16);

    // ---- phase 1: edge-parallel g/bs into smem (fused matvec, R11) ----
    {
        float4 rec = g_rec[p];
        scol[w][lane] = __float_as_int(rec.x);
        srow[w][lane] = g_erow[p];
        float s1p = rec.y, c1 = rec.z, t1 = rec.w;
        float emb[16];
        emb[0] = s1p;
        float sk = s1p, ck = c1;
#pragma unroll
        for (int k = 1; k < 16; k++) {
            float sn = fmaf(sk, c1,  ck * s1p);
            float cn = fmaf(ck, c1, -sk * t1);
            emb[k] = sn; sk = sn; ck = cn;
        }
        ull g2[8], b2[8];
#pragma unroll
        for (int i = 0; i < 8; i++) { g2[i] = sbg2[i]; b2[i] = sbs2[i]; }
#pragma unroll
        for (int k = 0; k < 16; k++) {
            ull dv2 = pk2(emb[k], emb[k]);
            const ulonglong2* wg = (const ulonglong2*)(sWg2 + k * 8);
            const ulonglong2* ws = (const ulonglong2*)(sWs2 + k * 8);
#pragma unroll
            for (int i = 0; i < 4; i++) {
                ulonglong2 wgp = wg[i], wsp = ws[i];
                g2[2 * i]     = fma2(dv2, wgp.x, g2[2 * i]);
                g2[2 * i + 1] = fma2(dv2, wgp.y, g2[2 * i + 1]);
                b2[2 * i]     = fma2(dv2, wsp.x, b2[2 * i]);
                b2[2 * i + 1] = fma2(dv2, wsp.y, b2[2 * i + 1]);
            }
        }
        float* slot = &smG[w][lane * SLOT];
#pragma unroll
        for (int i = 0; i < 8; i++) {
            float2 gv = upk(g2[i]);
            slot[2 * i]     = gv.x;
            slot[2 * i + 1] = gv.y;
            float2 bv = upk(b2[i]);
            slot[16 + 2 * i]     = bv.x;
            slot[16 + 2 * i + 1] = bv.y;
        }
    }
    __syncwarp();

    // ---- phase 2: two 16-edge batches; branch-free prefetch then ALU accumulate ----
    const float* smw = smG[w];
    const int* colw = scol[w];
    const int* roww = srow[w];
    int gidx = lane >> 1;
    float accR = 0.f, accS = 0.f;
    int cur = roww[0];
#pragma unroll
    for (int half = 0; half < 2; half++) {
        int base = half * 16;
        float yv[16], av[16];
#pragma unroll
        for (int e = 0; e < 16; e++) {
            int c = colw[base + e];
            yv[e] = __ldg(&g_y[(size_t)c * 32 + lane]);
            av[e] = sl ? __ldg(&g_as[(size_t)c * 16 + lane]) : 0.f;
        }
#pragma unroll
        for (int e = 0; e < 16; e++) {
            int idx = base + e;
            int r = roww[idx];
            if (r != cur) {
                red1(&g_aggR[(size_t)cur * 32 + lane], accR);
                if (sl) red1(&g_aggS[(size_t)cur * 16 + lane], accS);
                accR = 0.f; accS = 0.f; cur = r;
            }
            float gv = smw[idx * SLOT + gidx];
            accR = fmaf(gv, yv[e], accR);
            if (sl) accS += lrelu(av[e] + smw[idx * SLOT + 16 + lane]);
        }
    }
    red1(&g_aggR[(size_t)cur * 32 + lane], accR);
    if (sl) red1(&g_aggS[(size_t)cur * 16 + lane], accS);
}

// ---- readout: final post + rotate out + 48->144->6 MLP (f32x2) + graph scatter ----
__global__ void __launch_bounds__(256) kOut(
                     const float* __restrict__ W1, const float* __restrict__ b1,
                     const float* __restrict__ W2, const float* __restrict__ b2,
                     const int* __restrict__ batch, float* __restrict__ out) {
    __shared__ __align__(16) float sW1[48 * 144];
    __shared__ __align__(16) float sW2[144 * 6];
    __shared__ __align__(16) float sb1[144];
    __shared__ float sb2[8];
    for (int t = threadIdx.x; t < 48 * 144; t += blockDim.x) sW1[t] = W1[t];
    for (int t = threadIdx.x; t < 144 * 6; t += blockDim.x) sW2[t] = W2[t];
    for (int t = threadIdx.x; t < 144; t += blockDim.x) sb1[t] = b1[t];
    if (threadIdx.x < 6) sb2[threadIdx.x] = b2[threadIdx.x];
    if (threadIdx.x >= 6 && threadIdx.x < 8) sb2[threadIdx.x] = 0.f;
    __syncthreads();
    int n = blockIdx.x * blockDim.x + threadIdx.x;
    if (n >= NN) return;
    float invd = g_nacc[n * 4];
    float xc[48];
#pragma unroll
    for (int i = 0; i < 16; i++)
        xc[i] = g_xs[n * 16 + i] + g_aggS[n * 16 + i] * invd;
    float cc = g_ncs[2 * n], ss = g_ncs[2 * n + 1];
#pragma unroll
    for (int j = 0; j < 16; j++) {
        float gt = g_gate[n * 16 + j] * invd;
        float x0 = g_xrot[n * 32 + 2 * j]     + gt * g_aggR[n * 32 + 2 * j];
        float x1 = g_xrot[n * 32 + 2 * j + 1] + gt * g_aggR[n * 32 + 2 * j + 1];
        xc[16 + 2 * j]     = cc * x0 - ss * x1;
        xc[16 + 2 * j + 1] = ss * x0 + cc * x1;
    }
    ull u2[3];
    u2[0] = pk2(sb2[0], sb2[1]);
    u2[1] = pk2(sb2[2], sb2[3]);
    u2[2] = pk2(sb2[4], sb2[5]);
    for (int o = 0; o < 144; o += 4) {
        const ull* wb = (const ull*)&sb1[o];
        ull h01 = wb[0], h23 = wb[1];
#pragma unroll
        for (int k = 0; k < 48; k++) {
            const ull* wp = (const ull*)&sW1[k * 144 + o];
            ull xv2 = pk2(xc[k], xc[k]);
            h01 = fma2(xv2, wp[0], h01);
            h23 = fma2(xv2, wp[1], h23);
        }
        float2 ha = upk(h01), hb = upk(h23);
        float hv[4] = {lrelu(ha.x), lrelu(ha.y), lrelu(hb.x), lrelu(hb.y)};
#pragma unroll
        for (int j = 0; j < 4; j++) {
            ull hj2 = pk2(hv[j], hv[j]);
            const ull* w2p = (const ull*)&sW2[(o + j) * 6];
            u2[0] = fma2(hj2, w2p[0], u2[0]);
            u2[1] = fma2(hj2, w2p[1], u2[1]);
            u2[2] = fma2(hj2, w2p[2], u2[2]);
        }
    }
    int b = batch[n];
    float2 ua = upk(u2[0]), ub = upk(u2[1]), uc = upk(u2[2]);
    atomicAdd(&out[b * 6 + 0], ua.x);
    atomicAdd(&out[b * 6 + 1], ua.y);
    atomicAdd(&out[b * 6 + 2], ub.x);
    atomicAdd(&out[b * 6 + 3], ub.y);
    atomicAdd(&out[b * 6 + 4], uc.x);
    atomicAdd(&out[b * 6 + 5], uc.y);
}

extern "C" void kernel_launch(void* const* d_in, const int* in_sizes, int n_in,
                              void* d_out, int out_size) {
    const float* pos   = (const float*)d_in[0];
    const float* Wemb  = (const float*)d_in[1];
    const float* wse   = (const float*)d_in[2];
    const float* bse   = (const float*)d_in[3];
    const float* Wg    = (const float*)d_in[4];
    const float* bg    = (const float*)d_in[5];
    const float* Wmix  = (const float*)d_in[6];
    const float* Wgate = (const float*)d_in[7];
    const float* bgate = (const float*)d_in[8];
    const float* Ws1   = (const float*)d_in[9];
    const float* bs1   = (const float*)d_in[10];
    const float* W1    = (const float*)d_in[11];
    const float* b1    = (const float*)d_in[12];
    const float* W2    = (const float*)d_in[13];
    const float* b2    = (const float*)d_in[14];
    const int*   ei    = (const int*)d_in[15];
    const int*   batch = (const int*)d_in[16];
    float* out = (float*)d_out;

    int nb = (NN + 255) / 256;
    int eb = (NE + 255) / 256;

    kZero<<<1563, 256>>>(out);
    kGraphAcc<<<eb, 256>>>(pos, batch, ei);
    kCenterScan<<<NBLK, 256>>>(pos, batch);
    kScanB<<<1, 512>>>();
    kScanC<<<NBLK, 256>>>();
    kEdgeFill<<<eb, 256>>>(ei);
    for (int l = 0; l < 3; l++) {
        kNodeFuse<<<nb, 256>>>(wse, bse, Wemb, Wmix, Wgate, bgate, Ws1, l);
        kEdgeLayerC<<<NE / 128, 128>>>(Wg, bg, Ws1, bs1, l);
    }
    kOut<<<nb, 256>>>(W1, b1, W2, b2, batch, out);
}

// round 15
// speedup vs baseline: 1.0753x; 1.0041x over previous
#include <cuda_runtime.h>
#include <cuda_fp16.h>
#include <math.h>

#define NN 100000
#define NE 1600000
#define NG 1000
#define NBLK 391   // ceil(NN/256)
#define SLOT 33
typedef unsigned long long ull;

// ---- scratch (static device globals; no allocation) ----
__device__ __align__(128) float g_posg[NN * 2];
__device__ __align__(128) float g_ncs [NN * 2];
__device__ __align__(128) float g_nacc[NN * 4];
__device__ __align__(128) float g_gacc[NG * 4];
__device__ int   g_deg[NN];
__device__ int   g_rowstart[NN];
__device__ int   g_cursor[NN];
__device__ int   g_psum[512];
__device__ __align__(128) float4 g_rec[NE];   // col(bits), s1*invd, c1, s1*(d+eps)/sqrt2
__device__ int   g_erow[NE];
__device__ __align__(128) float  g_xs  [NN * 16];
__device__ __align__(128) float  g_xrot[NN * 32];
__device__ __align__(128) __half g_yh  [NN * 32];   // fp16 y rows: 64B each
__device__ __align__(128) __half g_ash [NN * 16];   // fp16 a_s rows: 32B each
__device__ __align__(128) float  g_gate[NN * 16];
__device__ __align__(128) float  g_aggR[NN * 32];
__device__ __align__(128) float  g_aggS[NN * 16];

__device__ __forceinline__ void red4(float* a, float x, float y, float z, float w) {
    asm volatile("red.global.add.v4.f32 [%0], {%1,%2,%3,%4};"
                 :: "l"(a), "f"(x), "f"(y), "f"(z), "f"(w));
}
__device__ __forceinline__ void red1(float* a, float v) {
    asm volatile("red.global.add.f32 [%0], %1;" :: "l"(a), "f"(v));
}
__device__ __forceinline__ float lrelu(float x) { return x > 0.f ? x : 0.01f * x; }
__device__ __forceinline__ ull fma2(ull a, ull b, ull c) {
    ull d; asm("fma.rn.f32x2 %0,%1,%2,%3;" : "=l"(d) : "l"(a), "l"(b), "l"(c)); return d;
}
__device__ __forceinline__ ull pk2(float x, float y) {
    ull r; asm("mov.b64 %0,{%1,%2};" : "=l"(r) : "f"(x), "f"(y)); return r;
}
__device__ __forceinline__ float2 upk(ull v) {
    float2 r; asm("mov.b64 {%0,%1},%2;" : "=f"(r.x), "=f"(r.y) : "l"(v)); return r;
}

// ---- zero ----
__global__ void kZero(float* out) {
    int i = blockIdx.x * blockDim.x + threadIdx.x;
    for (int t = i; t < NN * 4; t += gridDim.x * blockDim.x) g_nacc[t] = 0.f;
    for (int t = i; t < NN; t += gridDim.x * blockDim.x) g_deg[t] = 0;
    if (i < NG * 4) g_gacc[i] = 0.f;
    if (i < NG * 6) out[i] = 0.f;
}

// edge-grid: per-edge degree histogram; first NN threads also do graph mean acc
__global__ void kGraphAcc(const float* __restrict__ pos, const int* __restrict__ batch,
                          const int* __restrict__ ei) {
    int n = blockIdx.x * blockDim.x + threadIdx.x;
    if (n < NN)
        red4(&g_gacc[batch[n] * 4], pos[2 * n], pos[2 * n + 1], 1.f, 0.f);
    if (n < NE)
        atomicAdd(&g_deg[ei[n]], 1);
}

// fused: center/rot (independent) + block-local scan of degrees
__global__ void kCenterScan(const float* __restrict__ pos, const int* __restrict__ batch) {
    __shared__ int s[256];
    int n = blockIdx.x * 256 + threadIdx.x;
    int v = (n < NN) ? g_deg[n] : 0;
    s[threadIdx.x] = v; __syncthreads();
    for (int d = 1; d < 256; d <<= 1) {
        int t = (threadIdx.x >= d) ? s[threadIdx.x - d] : 0;
        __syncthreads();
        s[threadIdx.x] += t;
        __syncthreads();
    }
    if (n < NN) g_rowstart[n] = s[threadIdx.x] - v;
    if (threadIdx.x == 255) g_psum[blockIdx.x] = s[255];
    if (n >= NN) return;
    float4 ga = *(const float4*)&g_gacc[batch[n] * 4];
    float inv = 1.f / fmaxf(ga.z, 1.f);
    float px = pos[2 * n]     - ga.x * inv;
    float py = pos[2 * n + 1] - ga.y * inv;
    g_posg[2 * n] = px; g_posg[2 * n + 1] = py;
    float r2 = px * px + py * py;
    float c = 1.f, sv = 0.f;
    if (r2 > 0.f) { float ir = rsqrtf(r2); c = px * ir; sv = py * ir; }
    g_ncs[2 * n] = c; g_ncs[2 * n + 1] = sv;
}

__global__ void kScanB() {
    __shared__ int s[512];
    int t = threadIdx.x;
    int v = (t < NBLK) ? g_psum[t] : 0;
    s[t] = v; __syncthreads();
    for (int d = 1; d < 512; d <<= 1) {
        int u = (t >= d) ? s[t - d] : 0;
        __syncthreads();
        s[t] += u;
        __syncthreads();
    }
    if (t < NBLK) g_psum[t] = s[t] - v;
}

__global__ void kScanC() {
    int n = blockIdx.x * 256 + threadIdx.x;
    if (n >= NN) return;
    int rs = g_rowstart[n] + g_psum[blockIdx.x];
    g_rowstart[n] = rs;
    g_cursor[n] = rs;
}

// ---- per-edge geometry + CSR fill ----
__global__ void kEdgeFill(const int* __restrict__ ei) {
    int e = blockIdx.x * blockDim.x + threadIdx.x;
    if (e >= NE) return;
    int r = ei[e], c = ei[NE + e];
    float vx = g_posg[2 * r] - g_posg[2 * c];
    float vy = g_posg[2 * r + 1] - g_posg[2 * c + 1];
    float r2 = vx * vx + vy * vy;
    float d = 0.f, cc = 1.f, ss = 0.f;
    if (r2 > 0.f) { float ir = rsqrtf(r2); d = r2 * ir; cc = vx * ir; ss = vy * ir; }
    float invd = 1.41421356237f / (d + 1e-8f);
    float s1, c1;
    __sincosf(3.14159265358979f * d, &s1, &c1);
    int pos = atomicAdd(&g_cursor[r], 1);
    g_rec[pos] = make_float4(__int_as_float(c), s1 * invd, c1,
                             s1 * (d + 1e-8f) * 0.70710678118f);
    g_erow[pos] = r;
    red4(&g_nacc[r * 4], 1.f, d, cc, ss);
}

// ---- fused node kernel: post(prev) / init + pre(layer); zero agg ----
__global__ void kNodeFuse(const float* __restrict__ wse, const float* __restrict__ bse,
                          const float* __restrict__ Wemb,
                          const float* __restrict__ Wmix, const float* __restrict__ Wgate,
                          const float* __restrict__ bgate, const float* __restrict__ Ws1,
                          int layer) {
    __shared__ __align__(16) ull sMix2[256];   // Wmix[i][j] duplicated into both halves
    __shared__ __align__(16) ull sGate2[128], sWs2[128];
    __shared__ ull sbg2[8];
    for (int t = threadIdx.x; t < 256; t += blockDim.x) {
        float w = Wmix[layer * 256 + t];
        sMix2[t] = pk2(w, w);
    }
    for (int t = threadIdx.x; t < 128; t += blockDim.x) {
        sGate2[t] = ((const ull*)(Wgate + layer * 256))[t];
        sWs2[t]   = ((const ull*)(Ws1 + layer * 512))[t];
    }
    if (threadIdx.x < 8) sbg2[threadIdx.x] = ((const ull*)(bgate + layer * 16))[threadIdx.x];
    __syncthreads();
    int n = blockIdx.x * blockDim.x + threadIdx.x;
    if (n >= NN) return;

    float xs[16], xr[32];
    if (layer == 0) {
        float4 a = *(const float4*)&g_nacc[n * 4];
        float deg = fmaxf(a.x, 1.f);
        float invdeg = 1.f / deg;
        float dmean = a.y * invdeg;
        float Cm = a.z * invdeg, Sm = a.w * invdeg;
#pragma unroll
        for (int i = 0; i < 16; i++) xs[i] = lrelu(dmean * wse[i] + bse[i]);
#pragma unroll
        for (int j = 0; j < 16; j++) {
            float w0 = Wemb[2 * j], w1 = Wemb[2 * j + 1];
            xr[2 * j]     = Cm * w0 - Sm * w1;
            xr[2 * j + 1] = Sm * w0 + Cm * w1;
        }
        g_nacc[n * 4] = invdeg;
        float4* po = (float4*)&g_xs[n * 16];
#pragma unroll
        for (int q = 0; q < 4; q++) po[q] = make_float4(xs[4*q], xs[4*q+1], xs[4*q+2], xs[4*q+3]);
        float4* pr = (float4*)&g_xrot[n * 32];
#pragma unroll
        for (int q = 0; q < 8; q++) pr[q] = make_float4(xr[4*q], xr[4*q+1], xr[4*q+2], xr[4*q+3]);
    } else {
        const float4* p = (const float4*)&g_xs[n * 16];
#pragma unroll
        for (int q = 0; q < 4; q++) { float4 v = p[q]; xs[4*q]=v.x; xs[4*q+1]=v.y; xs[4*q+2]=v.z; xs[4*q+3]=v.w; }
        const float4* pr = (const float4*)&g_xrot[n * 32];
#pragma unroll
        for (int q = 0; q < 8; q++) { float4 v = pr[q]; xr[4*q]=v.x; xr[4*q+1]=v.y; xr[4*q+2]=v.z; xr[4*q+3]=v.w; }
        float invd = g_nacc[n * 4];
#pragma unroll
        for (int j = 0; j < 16; j++) {
            float gt = g_gate[n * 16 + j] * invd;
            xr[2 * j]     += gt * g_aggR[n * 32 + 2 * j];
            xr[2 * j + 1] += gt * g_aggR[n * 32 + 2 * j + 1];
        }
#pragma unroll
        for (int i = 0; i < 16; i++) xs[i] += g_aggS[n * 16 + i] * invd;
        float4* po = (float4*)&g_xs[n * 16];
#pragma unroll
        for (int q = 0; q < 4; q++) po[q] = make_float4(xs[4*q], xs[4*q+1], xs[4*q+2], xs[4*q+3]);
        float4* pw = (float4*)&g_xrot[n * 32];
#pragma unroll
        for (int q = 0; q < 8; q++) pw[q] = make_float4(xr[4*q], xr[4*q+1], xr[4*q+2], xr[4*q+3]);
    }

    // y = Wmix @ x_rot  (packed, vectorized weight loads) -> fp16 store
    ull xr2[16];
#pragma unroll
    for (int j = 0; j < 16; j++) xr2[j] = pk2(xr[2 * j], xr[2 * j + 1]);
    __half2* yo = (__half2*)&g_yh[(size_t)n * 32];
#pragma unroll
    for (int i = 0; i < 16; i++) {
        ull acc = 0ull;
        const ulonglong2* wm = (const ulonglong2*)(sMix2 + i * 16);
#pragma unroll
        for (int j = 0; j < 8; j++) {
            ulonglong2 wp = wm[j];
            acc = fma2(wp.x, xr2[2 * j], acc);
            acc = fma2(wp.y, xr2[2 * j + 1], acc);
        }
        float2 av = upk(acc);
        yo[i] = __floats2half2_rn(av.x, av.y);
    }
    ull gt2[8], as2[8];
#pragma unroll
    for (int i = 0; i < 8; i++) { gt2[i] = sbg2[i]; as2[i] = 0ull; }
#pragma unroll
    for (int k = 0; k < 16; k++) {
        ull xv2 = pk2(xs[k], xs[k]);
        const ulonglong2* wg = (const ulonglong2*)(sGate2 + k * 8);
        const ulonglong2* ws = (const ulonglong2*)(sWs2 + k * 8);
#pragma unroll
        for (int i = 0; i < 4; i++) {
            ulonglong2 wgp = wg[i], wsp = ws[i];
            gt2[2 * i]     = fma2(xv2, wgp.x, gt2[2 * i]);
            gt2[2 * i + 1] = fma2(xv2, wgp.y, gt2[2 * i + 1]);
            as2[2 * i]     = fma2(xv2, wsp.x, as2[2 * i]);
            as2[2 * i + 1] = fma2(xv2, wsp.y, as2[2 * i + 1]);
        }
    }
    __half2* ao = (__half2*)&g_ash[(size_t)n * 16];
#pragma unroll
    for (int i = 0; i < 8; i++) {
        float2 gv = upk(gt2[i]);
        g_gate[n * 16 + 2 * i]     = 1.f / (1.f + __expf(-gv.x));
        g_gate[n * 16 + 2 * i + 1] = 1.f / (1.f + __expf(-gv.y));
        float2 av = upk(as2[i]);
        ao[i] = __floats2half2_rn(av.x, av.y);
    }
    // zero accumulators for this layer's edge pass
    float4 z = make_float4(0.f, 0.f, 0.f, 0.f);
    float4* ar = (float4*)&g_aggR[n * 32];
#pragma unroll
    for (int q = 0; q < 8; q++) ar[q] = z;
    float4* as4 = (float4*)&g_aggS[n * 16];
#pragma unroll
    for (int q = 0; q < 4; q++) as4[q] = z;
}

// ---- per-edge layer (hot): warp = 32 CSR edges; fp16 coalesced gathers ----
__global__ void __launch_bounds__(128, 7) kEdgeLayerC(
                           const float* __restrict__ Wg, const float* __restrict__ bg,
                           const float* __restrict__ Ws1, const float* __restrict__ bs1,
                           int layer) {
    __shared__ __align__(16) ull sWg2[128], sWs2[128];
    __shared__ ull sbg2[8], sbs2[8];
    __shared__ float smG[4][32 * SLOT];
    __shared__ int scol[4][32], srow[4][32];
    for (int t = threadIdx.x; t < 128; t += blockDim.x) {
        sWg2[t] = ((const ull*)(Wg + layer * 256))[t];
        sWs2[t] = ((const ull*)(Ws1 + layer * 512 + 256))[t];
    }
    if (threadIdx.x < 8) {
        sbg2[threadIdx.x] = ((const ull*)(bg + layer * 16))[threadIdx.x];
        sbs2[threadIdx.x] = ((const ull*)(bs1 + layer * 16))[threadIdx.x];
    }
    __syncthreads();
    int w = threadIdx.x >> 5;
    int lane = threadIdx.x & 31;
    int p = blockIdx.x * 128 + threadIdx.x;   // NE % 128 == 0
    bool sl = (lane < 16);

    // ---- phase 1: edge-parallel g/bs into smem (fused matvec) ----
    {
        float4 rec = g_rec[p];
        scol[w][lane] = __float_as_int(rec.x);
        srow[w][lane] = g_erow[p];
        float s1p = rec.y, c1 = rec.z, t1 = rec.w;
        float emb[16];
        emb[0] = s1p;
        float sk = s1p, ck = c1;
#pragma unroll
        for (int k = 1; k < 16; k++) {
            float sn = fmaf(sk, c1,  ck * s1p);
            float cn = fmaf(ck, c1, -sk * t1);
            emb[k] = sn; sk = sn; ck = cn;
        }
        ull g2[8], b2[8];
#pragma unroll
        for (int i = 0; i < 8; i++) { g2[i] = sbg2[i]; b2[i] = sbs2[i]; }
#pragma unroll
        for (int k = 0; k < 16; k++) {
            ull dv2 = pk2(emb[k], emb[k]);
            const ulonglong2* wg = (const ulonglong2*)(sWg2 + k * 8);
            const ulonglong2* ws = (const ulonglong2*)(sWs2 + k * 8);
#pragma unroll
            for (int i = 0; i < 4; i++) {
                ulonglong2 wgp = wg[i], wsp = ws[i];
                g2[2 * i]     = fma2(dv2, wgp.x, g2[2 * i]);
                g2[2 * i + 1] = fma2(dv2, wgp.y, g2[2 * i + 1]);
                b2[2 * i]     = fma2(dv2, wsp.x, b2[2 * i]);
                b2[2 * i + 1] = fma2(dv2, wsp.y, b2[2 * i + 1]);
            }
        }
        float* slot = &smG[w][lane * SLOT];
#pragma unroll
        for (int i = 0; i < 8; i++) {
            float2 gv = upk(g2[i]);
            slot[2 * i]     = gv.x;
            slot[2 * i + 1] = gv.y;
            float2 bv = upk(b2[i]);
            slot[16 + 2 * i]     = bv.x;
            slot[16 + 2 * i + 1] = bv.y;
        }
    }
    __syncwarp();

    // ---- phase 2: two 16-edge batches; branch-free fp16 prefetch then ALU accumulate ----
    const float* smw = smG[w];
    const int* colw = scol[w];
    const int* roww = srow[w];
    int gidx = lane >> 1;
    float accR = 0.f, accS = 0.f;
    int cur = roww[0];
#pragma unroll
    for (int half = 0; half < 2; half++) {
        int base = half * 16;
        float yv[16], av[16];
#pragma unroll
        for (int e = 0; e < 16; e++) {
            int c = colw[base + e];
            yv[e] = __half2float(__ldg(&g_yh[(size_t)c * 32 + lane]));
            av[e] = sl ? __half2float(__ldg(&g_ash[(size_t)c * 16 + lane])) : 0.f;
        }
#pragma unroll
        for (int e = 0; e < 16; e++) {
            int idx = base + e;
            int r = roww[idx];
            if (r != cur) {
                red1(&g_aggR[(size_t)cur * 32 + lane], accR);
                if (sl) red1(&g_aggS[(size_t)cur * 16 + lane], accS);
                accR = 0.f; accS = 0.f; cur = r;
            }
            float gv = smw[idx * SLOT + gidx];
            accR = fmaf(gv, yv[e], accR);
            if (sl) accS += lrelu(av[e] + smw[idx * SLOT + 16 + lane]);
        }
    }
    red1(&g_aggR[(size_t)cur * 32 + lane], accR);
    if (sl) red1(&g_aggS[(size_t)cur * 16 + lane], accS);
}

// ---- readout: final post + rotate out + 48->144->6 MLP (f32x2) + graph scatter ----
__global__ void __launch_bounds__(256) kOut(
                     const float* __restrict__ W1, const float* __restrict__ b1,
                     const float* __restrict__ W2, const float* __restrict__ b2,
                     const int* __restrict__ batch, float* __restrict__ out) {
    __shared__ __align__(16) float sW1[48 * 144];
    __shared__ __align__(16) float sW2[144 * 6];
    __shared__ __align__(16) float sb1[144];
    __shared__ float sb2[8];
    for (int t = threadIdx.x; t < 48 * 144; t += blockDim.x) sW1[t] = W1[t];
    for (int t = threadIdx.x; t < 144 * 6; t += blockDim.x) sW2[t] = W2[t];
    for (int t = threadIdx.x; t < 144; t += blockDim.x) sb1[t] = b1[t];
    if (threadIdx.x < 6) sb2[threadIdx.x] = b2[threadIdx.x];
    if (threadIdx.x >= 6 && threadIdx.x < 8) sb2[threadIdx.x] = 0.f;
    __syncthreads();
    int n = blockIdx.x * blockDim.x + threadIdx.x;
    if (n >= NN) return;
    float invd = g_nacc[n * 4];
    float xc[48];
#pragma unroll
    for (int i = 0; i < 16; i++)
        xc[i] = g_xs[n * 16 + i] + g_aggS[n * 16 + i] * invd;
    float cc = g_ncs[2 * n], ss = g_ncs[2 * n + 1];
#pragma unroll
    for (int j = 0; j < 16; j++) {
        float gt = g_gate[n * 16 + j] * invd;
        float x0 = g_xrot[n * 32 + 2 * j]     + gt * g_aggR[n * 32 + 2 * j];
        float x1 = g_xrot[n * 32 + 2 * j + 1] + gt * g_aggR[n * 32 + 2 * j + 1];
        xc[16 + 2 * j]     = cc * x0 - ss * x1;
        xc[16 + 2 * j + 1] = ss * x0 + cc * x1;
    }
    ull u2[3];
    u2[0] = pk2(sb2[0], sb2[1]);
    u2[1] = pk2(sb2[2], sb2[3]);
    u2[2] = pk2(sb2[4], sb2[5]);
    for (int o = 0; o < 144; o += 4) {
        const ull* wb = (const ull*)&sb1[o];
        ull h01 = wb[0], h23 = wb[1];
#pragma unroll
        for (int k = 0; k < 48; k++) {
            const ull* wp = (const ull*)&sW1[k * 144 + o];
            ull xv2 = pk2(xc[k], xc[k]);
            h01 = fma2(xv2, wp[0], h01);
            h23 = fma2(xv2, wp[1], h23);
        }
        float2 ha = upk(h01), hb = upk(h23);
        float hv[4] = {lrelu(ha.x), lrelu(ha.y), lrelu(hb.x), lrelu(hb.y)};
#pragma unroll
        for (int j = 0; j < 4; j++) {
            ull hj2 = pk2(hv[j], hv[j]);
            const ull* w2p = (const ull*)&sW2[(o + j) * 6];
            u2[0] = fma2(hj2, w2p[0], u2[0]);
            u2[1] = fma2(hj2, w2p[1], u2[1]);
            u2[2] = fma2(hj2, w2p[2], u2[2]);
        }
    }
    int b = batch[n];
    float2 ua = upk(u2[0]), ub = upk(u2[1]), uc = upk(u2[2]);
    atomicAdd(&out[b * 6 + 0], ua.x);
    atomicAdd(&out[b * 6 + 1], ua.y);
    atomicAdd(&out[b * 6 + 2], ub.x);
    atomicAdd(&out[b * 6 + 3], ub.y);
    atomicAdd(&out[b * 6 + 4], uc.x);
    atomicAdd(&out[b * 6 + 5], uc.y);
}

extern "C" void kernel_launch(void* const* d_in, const int* in_sizes, int n_in,
                              void* d_out, int out_size) {
    const float* pos   = (const float*)d_in[0];
    const float* Wemb  = (const float*)d_in[1];
    const float* wse   = (const float*)d_in[2];
    const float* bse   = (const float*)d_in[3];
    const float* Wg    = (const float*)d_in[4];
    const float* bg    = (const float*)d_in[5];
    const float* Wmix  = (const float*)d_in[6];
    const float* Wgate = (const float*)d_in[7];
    const float* bgate = (const float*)d_in[8];
    const float* Ws1   = (const float*)d_in[9];
    const float* bs1   = (const float*)d_in[10];
    const float* W1    = (const float*)d_in[11];
    const float* b1    = (const float*)d_in[12];
    const float* W2    = (const float*)d_in[13];
    const float* b2    = (const float*)d_in[14];
    const int*   ei    = (const int*)d_in[15];
    const int*   batch = (const int*)d_in[16];
    float* out = (float*)d_out;

    int nb = (NN + 255) / 256;
    int eb = (NE + 255) / 256;

    kZero<<<1563, 256>>>(out);
    kGraphAcc<<<eb, 256>>>(pos, batch, ei);
    kCenterScan<<<NBLK, 256>>>(pos, batch);
    kScanB<<<1, 512>>>();
    kScanC<<<NBLK, 256>>>();
    kEdgeFill<<<eb, 256>>>(ei);
    for (int l = 0; l < 3; l++) {
        kNodeFuse<<<nb, 256>>>(wse, bse, Wemb, Wmix, Wgate, bgate, Ws1, l);
        kEdgeLayerC<<<NE / 128, 128>>>(Wg, bg, Ws1, bs1, l);
    }
    kOut<<<nb, 256>>>(W1, b1, W2, b2, batch, out);
}

// round 16
// speedup vs baseline: 1.2020x; 1.1178x over previous
#include <cuda_runtime.h>
#include <cuda_fp16.h>
#include <math.h>

#define NN 100000
#define NE 1600000
#define NG 1000
#define NBLK 391   // ceil(NN/256)
#define TROWS 65537          // 65536 bins over [0,8] + 1 zero-d row
#define TSCALE 8192.0f       // bins per unit distance
typedef unsigned long long ull;

// ---- scratch (static device globals; no allocation) ----
__device__ __align__(128) float g_posg[NN * 2];
__device__ __align__(128) float g_ncs [NN * 2];
__device__ __align__(128) float g_nacc[NN * 4];
__device__ __align__(128) float g_gacc[NG * 4];
__device__ int   g_deg[NN];
__device__ int   g_rowstart[NN];
__device__ int   g_cursor[NN];
__device__ int   g_psum[512];
__device__ __align__(128) int2  g_reci[NE];         // (col, table idx)
__device__ int   g_erow[NE];
__device__ __align__(128) float  g_xs  [NN * 16];
__device__ __align__(128) float  g_xrot[NN * 32];
__device__ __align__(128) __half g_yh  [NN * 32];   // fp16 y rows: 64B
__device__ __align__(128) __half g_ash [NN * 16];   // fp16 a_s rows: 32B
__device__ __align__(128) float  g_gate[NN * 16];
__device__ __align__(128) float  g_aggR[NN * 32];
__device__ __align__(128) float  g_aggS[NN * 16];
__device__ __align__(128) float  g_tab [3 * TROWS * 32];  // per-layer g/bs table

__device__ __forceinline__ void red4(float* a, float x, float y, float z, float w) {
    asm volatile("red.global.add.v4.f32 [%0], {%1,%2,%3,%4};"
                 :: "l"(a), "f"(x), "f"(y), "f"(z), "f"(w));
}
__device__ __forceinline__ void red1(float* a, float v) {
    asm volatile("red.global.add.f32 [%0], %1;" :: "l"(a), "f"(v));
}
__device__ __forceinline__ float lrelu(float x) { return x > 0.f ? x : 0.01f * x; }
__device__ __forceinline__ ull fma2(ull a, ull b, ull c) {
    ull d; asm("fma.rn.f32x2 %0,%1,%2,%3;" : "=l"(d) : "l"(a), "l"(b), "l"(c)); return d;
}
__device__ __forceinline__ ull pk2(float x, float y) {
    ull r; asm("mov.b64 %0,{%1,%2};" : "=l"(r) : "f"(x), "f"(y)); return r;
}
__device__ __forceinline__ float2 upk(ull v) {
    float2 r; asm("mov.b64 {%0,%1},%2;" : "=f"(r.x), "=f"(r.y) : "l"(v)); return r;
}

// ---- zero ----
__global__ void kZero(float* out) {
    int i = blockIdx.x * blockDim.x + threadIdx.x;
    for (int t = i; t < NN * 4; t += gridDim.x * blockDim.x) g_nacc[t] = 0.f;
    for (int t = i; t < NN; t += gridDim.x * blockDim.x) g_deg[t] = 0;
    if (i < NG * 4) g_gacc[i] = 0.f;
    if (i < NG * 6) out[i] = 0.f;
}

__global__ void kGraphAcc(const float* __restrict__ pos, const int* __restrict__ batch,
                          const int* __restrict__ ei) {
    int n = blockIdx.x * blockDim.x + threadIdx.x;
    if (n < NN)
        red4(&g_gacc[batch[n] * 4], pos[2 * n], pos[2 * n + 1], 1.f, 0.f);
    if (n < NE)
        atomicAdd(&g_deg[ei[n]], 1);
}

// ---- build g/bs tables: one row per (layer, d-bin) ----
__global__ void __launch_bounds__(128) kTabBuild(
        const float* __restrict__ Wg, const float* __restrict__ bg,
        const float* __restrict__ Ws1, const float* __restrict__ bs1) {
    const int BPL = (TROWS + 127) / 128;   // blocks per layer = 513
    int layer = blockIdx.x / BPL;
    int idx = (blockIdx.x % BPL) * 128 + threadIdx.x;
    __shared__ __align__(16) ull sWg2[128], sWs2[128];
    __shared__ ull sbg2[8], sbs2[8];
    for (int t = threadIdx.x; t < 128; t += blockDim.x) {
        sWg2[t] = ((const ull*)(Wg + layer * 256))[t];
        sWs2[t] = ((const ull*)(Ws1 + layer * 512 + 256))[t];
    }
    if (threadIdx.x < 8) {
        sbg2[threadIdx.x] = ((const ull*)(bg + layer * 16))[threadIdx.x];
        sbs2[threadIdx.x] = ((const ull*)(bs1 + layer * 16))[threadIdx.x];
    }
    __syncthreads();
    if (idx >= TROWS) return;
    float d = (idx == TROWS - 1) ? 0.f : ((float)idx + 0.5f) / TSCALE;
    float denom = 1.41421356237f / (d + 1e-8f);
    float s1, c1;
    sincosf(3.14159265358979f * d, &s1, &c1);
    float emb[16];
    float sk = s1, ck = c1;
    emb[0] = s1 * denom;
#pragma unroll
    for (int k = 1; k < 16; k++) {
        float sn = fmaf(sk, c1,  ck * s1);
        float cn = fmaf(ck, c1, -sk * s1);
        emb[k] = sn * denom; sk = sn; ck = cn;
    }
    ull g2[8], b2[8];
#pragma unroll
    for (int i = 0; i < 8; i++) { g2[i] = sbg2[i]; b2[i] = sbs2[i]; }
#pragma unroll
    for (int k = 0; k < 16; k++) {
        ull dv2 = pk2(emb[k], emb[k]);
        const ulonglong2* wg = (const ulonglong2*)(sWg2 + k * 8);
        const ulonglong2* ws = (const ulonglong2*)(sWs2 + k * 8);
#pragma unroll
        for (int i = 0; i < 4; i++) {
            ulonglong2 wgp = wg[i], wsp = ws[i];
            g2[2 * i]     = fma2(dv2, wgp.x, g2[2 * i]);
            g2[2 * i + 1] = fma2(dv2, wgp.y, g2[2 * i + 1]);
            b2[2 * i]     = fma2(dv2, wsp.x, b2[2 * i]);
            b2[2 * i + 1] = fma2(dv2, wsp.y, b2[2 * i + 1]);
        }
    }
    float* row = g_tab + ((size_t)layer * TROWS + idx) * 32;
    ull* row2 = (ull*)row;
#pragma unroll
    for (int i = 0; i < 8; i++) {
        row2[i] = g2[i];        // row[0..15] = g
        row2[8 + i] = b2[i];    // row[16..31] = bs
    }
}

// fused: center/rot (independent) + block-local scan of degrees
__global__ void kCenterScan(const float* __restrict__ pos, const int* __restrict__ batch) {
    __shared__ int s[256];
    int n = blockIdx.x * 256 + threadIdx.x;
    int v = (n < NN) ? g_deg[n] : 0;
    s[threadIdx.x] = v; __syncthreads();
    for (int d = 1; d < 256; d <<= 1) {
        int t = (threadIdx.x >= d) ? s[threadIdx.x - d] : 0;
        __syncthreads();
        s[threadIdx.x] += t;
        __syncthreads();
    }
    if (n < NN) g_rowstart[n] = s[threadIdx.x] - v;
    if (threadIdx.x == 255) g_psum[blockIdx.x] = s[255];
    if (n >= NN) return;
    float4 ga = *(const float4*)&g_gacc[batch[n] * 4];
    float inv = 1.f / fmaxf(ga.z, 1.f);
    float px = pos[2 * n]     - ga.x * inv;
    float py = pos[2 * n + 1] - ga.y * inv;
    g_posg[2 * n] = px; g_posg[2 * n + 1] = py;
    float r2 = px * px + py * py;
    float c = 1.f, sv = 0.f;
    if (r2 > 0.f) { float ir = rsqrtf(r2); c = px * ir; sv = py * ir; }
    g_ncs[2 * n] = c; g_ncs[2 * n + 1] = sv;
}

__global__ void kScanB() {
    __shared__ int s[512];
    int t = threadIdx.x;
    int v = (t < NBLK) ? g_psum[t] : 0;
    s[t] = v; __syncthreads();
    for (int d = 1; d < 512; d <<= 1) {
        int u = (t >= d) ? s[t - d] : 0;
        __syncthreads();
        s[t] += u;
        __syncthreads();
    }
    if (t < NBLK) g_psum[t] = s[t] - v;
}

__global__ void kScanC() {
    int n = blockIdx.x * 256 + threadIdx.x;
    if (n >= NN) return;
    int rs = g_rowstart[n] + g_psum[blockIdx.x];
    g_rowstart[n] = rs;
    g_cursor[n] = rs;
}

// ---- per-edge geometry + CSR fill (no sincos; stores table idx) ----
__global__ void kEdgeFill(const int* __restrict__ ei) {
    int e = blockIdx.x * blockDim.x + threadIdx.x;
    if (e >= NE) return;
    int r = ei[e], c = ei[NE + e];
    float vx = g_posg[2 * r] - g_posg[2 * c];
    float vy = g_posg[2 * r + 1] - g_posg[2 * c + 1];
    float r2 = vx * vx + vy * vy;
    float d = 0.f, cc = 1.f, ss = 0.f;
    int idx = TROWS - 1;  // zero-distance row
    if (r2 > 0.f) {
        float ir = rsqrtf(r2);
        d = r2 * ir; cc = vx * ir; ss = vy * ir;
        idx = min((int)(d * TSCALE), TROWS - 2);
    }
    int pos = atomicAdd(&g_cursor[r], 1);
    g_reci[pos] = make_int2(c, idx);
    g_erow[pos] = r;
    red4(&g_nacc[r * 4], 1.f, d, cc, ss);
}

// ---- fused node kernel: post(prev) / init + pre(layer); zero agg ----
__global__ void kNodeFuse(const float* __restrict__ wse, const float* __restrict__ bse,
                          const float* __restrict__ Wemb,
                          const float* __restrict__ Wmix, const float* __restrict__ Wgate,
                          const float* __restrict__ bgate, const float* __restrict__ Ws1,
                          int layer) {
    __shared__ __align__(16) ull sMix2[256];
    __shared__ __align__(16) ull sGate2[128], sWs2[128];
    __shared__ ull sbg2[8];
    for (int t = threadIdx.x; t < 256; t += blockDim.x) {
        float w = Wmix[layer * 256 + t];
        sMix2[t] = pk2(w, w);
    }
    for (int t = threadIdx.x; t < 128; t += blockDim.x) {
        sGate2[t] = ((const ull*)(Wgate + layer * 256))[t];
        sWs2[t]   = ((const ull*)(Ws1 + layer * 512))[t];
    }
    if (threadIdx.x < 8) sbg2[threadIdx.x] = ((const ull*)(bgate + layer * 16))[threadIdx.x];
    __syncthreads();
    int n = blockIdx.x * blockDim.x + threadIdx.x;
    if (n >= NN) return;

    float xs[16], xr[32];
    if (layer == 0) {
        float4 a = *(const float4*)&g_nacc[n * 4];
        float deg = fmaxf(a.x, 1.f);
        float invdeg = 1.f / deg;
        float dmean = a.y * invdeg;
        float Cm = a.z * invdeg, Sm = a.w * invdeg;
#pragma unroll
        for (int i = 0; i < 16; i++) xs[i] = lrelu(dmean * wse[i] + bse[i]);
#pragma unroll
        for (int j = 0; j < 16; j++) {
            float w0 = Wemb[2 * j], w1 = Wemb[2 * j + 1];
            xr[2 * j]     = Cm * w0 - Sm * w1;
            xr[2 * j + 1] = Sm * w0 + Cm * w1;
        }
        g_nacc[n * 4] = invdeg;
        float4* po = (float4*)&g_xs[n * 16];
#pragma unroll
        for (int q = 0; q < 4; q++) po[q] = make_float4(xs[4*q], xs[4*q+1], xs[4*q+2], xs[4*q+3]);
        float4* pr = (float4*)&g_xrot[n * 32];
#pragma unroll
        for (int q = 0; q < 8; q++) pr[q] = make_float4(xr[4*q], xr[4*q+1], xr[4*q+2], xr[4*q+3]);
    } else {
        const float4* p = (const float4*)&g_xs[n * 16];
#pragma unroll
        for (int q = 0; q < 4; q++) { float4 v = p[q]; xs[4*q]=v.x; xs[4*q+1]=v.y; xs[4*q+2]=v.z; xs[4*q+3]=v.w; }
        const float4* pr = (const float4*)&g_xrot[n * 32];
#pragma unroll
        for (int q = 0; q < 8; q++) { float4 v = pr[q]; xr[4*q]=v.x; xr[4*q+1]=v.y; xr[4*q+2]=v.z; xr[4*q+3]=v.w; }
        float invd = g_nacc[n * 4];
#pragma unroll
        for (int j = 0; j < 16; j++) {
            float gt = g_gate[n * 16 + j] * invd;
            xr[2 * j]     += gt * g_aggR[n * 32 + 2 * j];
            xr[2 * j + 1] += gt * g_aggR[n * 32 + 2 * j + 1];
        }
#pragma unroll
        for (int i = 0; i < 16; i++) xs[i] += g_aggS[n * 16 + i] * invd;
        float4* po = (float4*)&g_xs[n * 16];
#pragma unroll
        for (int q = 0; q < 4; q++) po[q] = make_float4(xs[4*q], xs[4*q+1], xs[4*q+2], xs[4*q+3]);
        float4* pw = (float4*)&g_xrot[n * 32];
#pragma unroll
        for (int q = 0; q < 8; q++) pw[q] = make_float4(xr[4*q], xr[4*q+1], xr[4*q+2], xr[4*q+3]);
    }

    // y = Wmix @ x_rot -> fp16
    ull xr2[16];
#pragma unroll
    for (int j = 0; j < 16; j++) xr2[j] = pk2(xr[2 * j], xr[2 * j + 1]);
    __half2* yo = (__half2*)&g_yh[(size_t)n * 32];
#pragma unroll
    for (int i = 0; i < 16; i++) {
        ull acc = 0ull;
        const ulonglong2* wm = (const ulonglong2*)(sMix2 + i * 16);
#pragma unroll
        for (int j = 0; j < 8; j++) {
            ulonglong2 wp = wm[j];
            acc = fma2(wp.x, xr2[2 * j], acc);
            acc = fma2(wp.y, xr2[2 * j + 1], acc);
        }
        float2 av = upk(acc);
        yo[i] = __floats2half2_rn(av.x, av.y);
    }
    ull gt2[8], as2[8];
#pragma unroll
    for (int i = 0; i < 8; i++) { gt2[i] = sbg2[i]; as2[i] = 0ull; }
#pragma unroll
    for (int k = 0; k < 16; k++) {
        ull xv2 = pk2(xs[k], xs[k]);
        const ulonglong2* wg = (const ulonglong2*)(sGate2 + k * 8);
        const ulonglong2* ws = (const ulonglong2*)(sWs2 + k * 8);
#pragma unroll
        for (int i = 0; i < 4; i++) {
            ulonglong2 wgp = wg[i], wsp = ws[i];
            gt2[2 * i]     = fma2(xv2, wgp.x, gt2[2 * i]);
            gt2[2 * i + 1] = fma2(xv2, wgp.y, gt2[2 * i + 1]);
            as2[2 * i]     = fma2(xv2, wsp.x, as2[2 * i]);
            as2[2 * i + 1] = fma2(xv2, wsp.y, as2[2 * i + 1]);
        }
    }
    __half2* ao = (__half2*)&g_ash[(size_t)n * 16];
#pragma unroll
    for (int i = 0; i < 8; i++) {
        float2 gv = upk(gt2[i]);
        g_gate[n * 16 + 2 * i]     = 1.f / (1.f + __expf(-gv.x));
        g_gate[n * 16 + 2 * i + 1] = 1.f / (1.f + __expf(-gv.y));
        float2 av = upk(as2[i]);
        ao[i] = __floats2half2_rn(av.x, av.y);
    }
    float4 z = make_float4(0.f, 0.f, 0.f, 0.f);
    float4* ar = (float4*)&g_aggR[n * 32];
#pragma unroll
    for (int q = 0; q < 8; q++) ar[q] = z;
    float4* as4 = (float4*)&g_aggS[n * 16];
#pragma unroll
    for (int q = 0; q < 4; q++) as4[q] = z;
}

// ---- per-edge layer (hot): warp = 32 CSR edges; pure table-lookup, no matvec ----
__global__ void __launch_bounds__(128) kEdgeLayerT(int layer) {
    __shared__ ull sci[4][32];
    __shared__ int srow[4][32];
    int w = threadIdx.x >> 5;
    int lane = threadIdx.x & 31;
    int p = blockIdx.x * 128 + threadIdx.x;   // NE % 128 == 0
    bool sl = (lane < 16);
    int gidx = lane >> 1;

    int2 rec = g_reci[p];
    sci[w][lane] = ((ull)(unsigned)rec.y << 32) | (unsigned)rec.x;
    srow[w][lane] = g_erow[p];
    __syncwarp();

    const float* tab = g_tab + (size_t)layer * TROWS * 32;
    const ull* sciw = sci[w];
    const int* roww = srow[w];
    float accR = 0.f, accS = 0.f;
    int cur = roww[0];
#pragma unroll
    for (int qb = 0; qb < 4; qb++) {
        int base = qb * 8;
        float yv[8], av[8], gv[8], bv[8];
#pragma unroll
        for (int e = 0; e < 8; e++) {
            ull v = sciw[base + e];
            int c = (int)(unsigned)(v & 0xffffffffu);
            int ix = (int)(v >> 32);
            const float* row = tab + (size_t)ix * 32;
            gv[e] = __ldg(row + gidx);
            bv[e] = sl ? __ldg(row + 16 + lane) : 0.f;
            yv[e] = __half2float(__ldg(&g_yh[(size_t)c * 32 + lane]));
            av[e] = sl ? __half2float(__ldg(&g_ash[(size_t)c * 16 + lane])) : 0.f;
        }
#pragma unroll
        for (int e = 0; e < 8; e++) {
            int r = roww[base + e];
            if (r != cur) {
                red1(&g_aggR[(size_t)cur * 32 + lane], accR);
                if (sl) red1(&g_aggS[(size_t)cur * 16 + lane], accS);
                accR = 0.f; accS = 0.f; cur = r;
            }
            accR = fmaf(gv[e], yv[e], accR);
            if (sl) accS += lrelu(av[e] + bv[e]);
        }
    }
    red1(&g_aggR[(size_t)cur * 32 + lane], accR);
    if (sl) red1(&g_aggS[(size_t)cur * 16 + lane], accS);
}

// ---- readout: final post + rotate out + 48->144->6 MLP (f32x2) + graph scatter ----
__global__ void __launch_bounds__(256) kOut(
                     const float* __restrict__ W1, const float* __restrict__ b1,
                     const float* __restrict__ W2, const float* __restrict__ b2,
                     const int* __restrict__ batch, float* __restrict__ out) {
    __shared__ __align__(16) float sW1[48 * 144];
    __shared__ __align__(16) float sW2[144 * 6];
    __shared__ __align__(16) float sb1[144];
    __shared__ float sb2[8];
    for (int t = threadIdx.x; t < 48 * 144; t += blockDim.x) sW1[t] = W1[t];
    for (int t = threadIdx.x; t < 144 * 6; t += blockDim.x) sW2[t] = W2[t];
    for (int t = threadIdx.x; t < 144; t += blockDim.x) sb1[t] = b1[t];
    if (threadIdx.x < 6) sb2[threadIdx.x] = b2[threadIdx.x];
    if (threadIdx.x >= 6 && threadIdx.x < 8) sb2[threadIdx.x] = 0.f;
    __syncthreads();
    int n = blockIdx.x * blockDim.x + threadIdx.x;
    if (n >= NN) return;
    float invd = g_nacc[n * 4];
    float xc[48];
#pragma unroll
    for (int i = 0; i < 16; i++)
        xc[i] = g_xs[n * 16 + i] + g_aggS[n * 16 + i] * invd;
    float cc = g_ncs[2 * n], ss = g_ncs[2 * n + 1];
#pragma unroll
    for (int j = 0; j < 16; j++) {
        float gt = g_gate[n * 16 + j] * invd;
        float x0 = g_xrot[n * 32 + 2 * j]     + gt * g_aggR[n * 32 + 2 * j];
        float x1 = g_xrot[n * 32 + 2 * j + 1] + gt * g_aggR[n * 32 + 2 * j + 1];
        xc[16 + 2 * j]     = cc * x0 - ss * x1;
        xc[16 + 2 * j + 1] = ss * x0 + cc * x1;
    }
    ull u2[3];
    u2[0] = pk2(sb2[0], sb2[1]);
    u2[1] = pk2(sb2[2], sb2[3]);
    u2[2] = pk2(sb2[4], sb2[5]);
    for (int o = 0; o < 144; o += 4) {
        const ull* wb = (const ull*)&sb1[o];
        ull h01 = wb[0], h23 = wb[1];
#pragma unroll
        for (int k = 0; k < 48; k++) {
            const ull* wp = (const ull*)&sW1[k * 144 + o];
            ull xv2 = pk2(xc[k], xc[k]);
            h01 = fma2(xv2, wp[0], h01);
            h23 = fma2(xv2, wp[1], h23);
        }
        float2 ha = upk(h01), hb = upk(h23);
        float hv[4] = {lrelu(ha.x), lrelu(ha.y), lrelu(hb.x), lrelu(hb.y)};
#pragma unroll
        for (int j = 0; j < 4; j++) {
            ull hj2 = pk2(hv[j], hv[j]);
            const ull* w2p = (const ull*)&sW2[(o + j) * 6];
            u2[0] = fma2(hj2, w2p[0], u2[0]);
            u2[1] = fma2(hj2, w2p[1], u2[1]);
            u2[2] = fma2(hj2, w2p[2], u2[2]);
        }
    }
    int b = batch[n];
    float2 ua = upk(u2[0]), ub = upk(u2[1]), uc = upk(u2[2]);
    atomicAdd(&out[b * 6 + 0], ua.x);
    atomicAdd(&out[b * 6 + 1], ua.y);
    atomicAdd(&out[b * 6 + 2], ub.x);
    atomicAdd(&out[b * 6 + 3], ub.y);
    atomicAdd(&out[b * 6 + 4], uc.x);
    atomicAdd(&out[b * 6 + 5], uc.y);
}

extern "C" void kernel_launch(void* const* d_in, const int* in_sizes, int n_in,
                              void* d_out, int out_size) {
    const float* pos   = (const float*)d_in[0];
    const float* Wemb  = (const float*)d_in[1];
    const float* wse   = (const float*)d_in[2];
    const float* bse   = (const float*)d_in[3];
    const float* Wg    = (const float*)d_in[4];
    const float* bg    = (const float*)d_in[5];
    const float* Wmix  = (const float*)d_in[6];
    const float* Wgate = (const float*)d_in[7];
    const float* bgate = (const float*)d_in[8];
    const float* Ws1   = (const float*)d_in[9];
    const float* bs1   = (const float*)d_in[10];
    const float* W1    = (const float*)d_in[11];
    const float* b1    = (const float*)d_in[12];
    const float* W2    = (const float*)d_in[13];
    const float* b2    = (const float*)d_in[14];
    const int*   ei    = (const int*)d_in[15];
    const int*   batch = (const int*)d_in[16];
    float* out = (float*)d_out;

    int nb = (NN + 255) / 256;
    int eb = (NE + 255) / 256;
    const int BPL = (TROWS + 127) / 128;

    kZero<<<1563, 256>>>(out);
    kGraphAcc<<<eb, 256>>>(pos, batch, ei);
    kTabBuild<<<3 * BPL, 128>>>(Wg, bg, Ws1, bs1);
    kCenterScan<<<NBLK, 256>>>(pos, batch);
    kScanB<<<1, 512>>>();
    kScanC<<<NBLK, 256>>>();
    kEdgeFill<<<eb, 256>>>(ei);
    for (int l = 0; l < 3; l++) {
        kNodeFuse<<<nb, 256>>>(wse, bse, Wemb, Wmix, Wgate, bgate, Ws1, l);
        kEdgeLayerT<<<NE / 128, 128>>>(l);
    }
    kOut<<<nb, 256>>>(W1, b1, W2, b2, batch, out);
}